// round 8
// baseline (speedup 1.0000x reference)
#include <cuda_runtime.h>
#include <cuda_fp16.h>
#include <cstdint>
#include <math.h>

#define BB 16
#define CC 768
#define HWN 4096
#define DD 256
#define MM 32
#define SCALE 20.0f            // 1/EPS
#define NORMC (-8.32554830f)   // -log(32+4096)
#define VT_ELEMS (BB*MM*DD)

// ---- scratch (device globals; no allocations allowed) ----
__device__ float g_Z[BB*MM*HWN];     // 8 MB: Z[b,m,n]
__device__ float g_inv[BB*HWN];
__device__ float g_u[BB*MM];
__device__ float g_v[BB*HWN];
__device__ float g_wn[MM*DD];
// W as fp16 per-lane mma A-fragments: [dtile 16][ktile 48][lane 32][4 words]
__device__ __align__(16) unsigned g_wf[98304];

__device__ __forceinline__ uint32_t smem_u32(const void* p) {
    uint32_t a;
    asm("{ .reg .u64 t; cvta.to.shared.u64 t, %1; cvt.u32.u64 %0, t; }" : "=r"(a) : "l"(p));
    return a;
}

// fp16 split: a = hi + lo with |lo| <= 2^-11 |a|, fp16(hi), fp16(lo)
__device__ __forceinline__ void split2h(float a, float b, unsigned &hi, unsigned &lo) {
    __half ha = __float2half_rn(a), hb = __float2half_rn(b);
    float ra = a - __half2float(ha), rb = b - __half2float(hb);
    __half la = __float2half_rn(ra), lb = __float2half_rn(rb);
    hi = (unsigned)__half_as_ushort(ha) | ((unsigned)__half_as_ushort(hb) << 16);
    lo = (unsigned)__half_as_ushort(la) | ((unsigned)__half_as_ushort(lb) << 16);
}
__device__ __forceinline__ unsigned pack2h(float a, float b) {
    __half ha = __float2half_rn(a), hb = __float2half_rn(b);
    return (unsigned)__half_as_ushort(ha) | ((unsigned)__half_as_ushort(hb) << 16);
}

#define LDSM_T(r0,r1,r2,r3,addr) \
    asm volatile("ldmatrix.sync.aligned.m8n8.x4.trans.shared.b16 {%0,%1,%2,%3}, [%4];" \
        : "=r"(r0), "=r"(r1), "=r"(r2), "=r"(r3) : "r"(addr))

#define MMA_F16(acc, a, b0v, b1v) \
    asm volatile("mma.sync.aligned.m16n8k16.row.col.f32.f16.f16.f32 " \
        "{%0,%1,%2,%3}, {%4,%5,%6,%7}, {%8,%9}, {%0,%1,%2,%3};" \
        : "+f"((acc)[0]), "+f"((acc)[1]), "+f"((acc)[2]), "+f"((acc)[3]) \
        : "r"((a).x), "r"((a).y), "r"((a).z), "r"((a).w), "r"(b0v), "r"(b1v))

// ------------------------------------------------------------------
__global__ __launch_bounds__(256) void k_init(float* __restrict__ vt) {
    int i = blockIdx.x * 256 + threadIdx.x;
    if (i < BB*HWN) g_v[i] = 0.0f;
    if (i < VT_ELEMS) vt[i] = 0.0f;
}

// ------------------------------------------------------------------
__global__ __launch_bounds__(256) void k_wnorm(const float* __restrict__ v) {
    int r = blockIdx.x, t = threadIdx.x;
    float val = v[r*DD + t];
    float s = val * val;
    #pragma unroll
    for (int o = 16; o; o >>= 1) s += __shfl_xor_sync(~0u, s, o);
    __shared__ float red[8];
    if ((t & 31) == 0) red[t >> 5] = s;
    __syncthreads();
    if (t < 8) {
        float r2 = red[t];
        #pragma unroll
        for (int o = 4; o; o >>= 1) r2 += __shfl_xor_sync(0xff, r2, o, 8);
        if (t == 0) red[0] = r2;
    }
    __syncthreads();
    float inv = 1.0f / fmaxf(sqrtf(red[0]), 1e-12f);
    g_wn[r*DD + t] = val * inv;
}

// ------------------------------------------------------------------
// W -> fp16 per-lane A-fragment layout (single term).
//   d = dt*16 + (lane>>2) + (w&1)*8 ; c = kt*16 + (lane&3)*2 + (w>>1)*8
__global__ __launch_bounds__(256) void k_wsplit(const float* __restrict__ W) {
    int gid = blockIdx.x*256 + threadIdx.x;      // 0..98303
    int w = gid & 3, lane = (gid >> 2) & 31, tile = gid >> 7;
    int kt = tile % 48, dt = tile / 48;
    int d = dt*16 + (lane >> 2) + (w & 1)*8;
    int c = kt*16 + (lane & 3)*2 + (w >> 1)*8;
    g_wf[gid] = pack2h(W[(size_t)d*CC + c], W[(size_t)d*CC + c + 1]);
}

// ------------------------------------------------------------------
// k1_mma: x_proj[b,n,d] = W x + bias via mma.sync fp16 2-term x-split.
// CTA: 128 d x 128 n, 256 threads (8 warps), 2 CTAs/SM.
// Warp: 32 d x 64 n. Double-buffered x staging, 16-k chunks.
#define XPITCH 304                      // smem row pitch (bytes)
#define XLO    4864                     // hi->lo offset within buffer (16*304)
#define XBUF   9728                     // one x buffer (hi + lo)
#define EP_OFF 19456                    // epilogue staging region
#define EPITCH 132                      // epilogue float pitch (128 d + pad)
#define SMEM_SZ (EP_OFF + 64*EPITCH*4) // 53248

__global__ __launch_bounds__(256, 2) void k1_mma(const float* __restrict__ x,
                                                 const float* __restrict__ bias,
                                                 float* __restrict__ xp) {
    extern __shared__ char smc[];
    const uint32_t sb = smem_u32(smc);
    const int b = blockIdx.y >> 1, dh = blockIdx.y & 1;
    const int n0 = blockIdx.x * 128;
    const int t = threadIdx.x, w = t >> 5, lane = t & 31;
    const int nw = (w >> 2) * 64;

    float acc[2][8][4];
    #pragma unroll
    for (int mt = 0; mt < 2; ++mt)
        #pragma unroll
        for (int nt = 0; nt < 8; ++nt)
            #pragma unroll
            for (int i = 0; i < 4; ++i) acc[mt][nt][i] = 0.f;

    const float* xb = x + (size_t)b * CC * HWN + n0;
    const int c0 = t >> 5;              // staging row 0..7
    const int c1 = c0 + 8;              // staging row 8..15
    const int n4 = t & 31;              // float4 column

    // prefetch chunk 0 (16 k-rows)
    float4 v0 = *(const float4*)(xb + (size_t)c0*HWN + n4*4);
    float4 v1 = *(const float4*)(xb + (size_t)c1*HWN + n4*4);

    int buf = 0;
    for (int kc = 0; kc < CC; kc += 16, buf ^= 1) {
        // STS prefetched chunk into buf
        {
            char* base = smc + buf*XBUF;
            unsigned h01,l01,h23,l23;
            split2h(v0.x, v0.y, h01, l01);
            split2h(v0.z, v0.w, h23, l23);
            char* r0 = base + c0*XPITCH + n4*8;
            *(uint2*)r0         = make_uint2(h01, h23);
            *(uint2*)(r0 + XLO) = make_uint2(l01, l23);
            split2h(v1.x, v1.y, h01, l01);
            split2h(v1.z, v1.w, h23, l23);
            char* r1 = base + c1*XPITCH + n4*8;
            *(uint2*)r1         = make_uint2(h01, h23);
            *(uint2*)(r1 + XLO) = make_uint2(l01, l23);
        }
        // A-fragment loads for THIS chunk (gmem, independent of smem barrier)
        const int kt = kc >> 4;
        uint4 ah[2];
        #pragma unroll
        for (int mt = 0; mt < 2; ++mt) {
            int dt = dh*8 + (w & 3)*2 + mt;
            ah[mt] = *(const uint4*)(g_wf + ((dt*48 + kt)*32 + lane)*4);
        }
        // prefetch next x chunk (overlaps MMA below)
        if (kc + 16 < CC) {
            v0 = *(const float4*)(xb + (size_t)(kc + 16 + c0)*HWN + n4*4);
            v1 = *(const float4*)(xb + (size_t)(kc + 16 + c1)*HWN + n4*4);
        }
        __syncthreads();

        const uint32_t sxb = sb + buf*XBUF;
        #pragma unroll
        for (int j = 0; j < 4; ++j) {
            uint32_t baddr = sxb + (uint32_t)((lane & 15)*XPITCH
                           + (nw + j*16 + ((lane >> 4) << 3))*2);
            unsigned bh0,bh1,bh2,bh3, bl0,bl1,bl2,bl3;
            LDSM_T(bh0,bh1,bh2,bh3, baddr);
            LDSM_T(bl0,bl1,bl2,bl3, baddr + XLO);
            #pragma unroll
            for (int mt = 0; mt < 2; ++mt) {
                MMA_F16(acc[mt][2*j],   ah[mt], bh0, bh1);
                MMA_F16(acc[mt][2*j],   ah[mt], bl0, bl1);
                MMA_F16(acc[mt][2*j+1], ah[mt], bh2, bh3);
                MMA_F16(acc[mt][2*j+1], ah[mt], bl2, bl3);
            }
        }
        // next STS targets other buffer; safe without trailing sync
    }

    // epilogue: stage per 64-n half for coalesced stores of 128 d
    float* s_ep = (float*)(smc + EP_OFF);
    const float4* bias4 = (const float4*)bias;
    #pragma unroll
    for (int p = 0; p < 2; ++p) {
        __syncthreads();
        if ((w >> 2) == p) {
            #pragma unroll
            for (int mt = 0; mt < 2; ++mt) {
                int d = (w & 3)*32 + mt*16 + (lane >> 2);
                #pragma unroll
                for (int nt = 0; nt < 8; ++nt) {
                    int nl = nt*8 + (lane & 3)*2;
                    s_ep[nl*EPITCH + d]           = acc[mt][nt][0];
                    s_ep[(nl+1)*EPITCH + d]       = acc[mt][nt][1];
                    s_ep[nl*EPITCH + d + 8]       = acc[mt][nt][2];
                    s_ep[(nl+1)*EPITCH + d + 8]   = acc[mt][nt][3];
                }
            }
        }
        __syncthreads();
        #pragma unroll
        for (int i = 0; i < 8; ++i) {
            int idx = t + i*256;              // 2048 float4 items
            int row = idx >> 5, c4 = idx & 31;
            float4 v = *(float4*)(s_ep + row*EPITCH + c4*4);
            float4 bv = bias4[dh*32 + c4];
            v.x += bv.x; v.y += bv.y; v.z += bv.z; v.w += bv.w;
            *(float4*)(xp + (size_t)(b*HWN + n0 + p*64 + row)*DD + dh*128 + c4*4) = v;
        }
    }
}

// ------------------------------------------------------------------
// k1b: row L2 norms + cluster scores -> Z (reads x_proj)
__global__ __launch_bounds__(256) void k1b(const float* __restrict__ xp) {
    const int b = blockIdx.y, n0 = blockIdx.x * 64;
    const int t = threadIdx.x, tx = t & 15, ty = t >> 4;
    __shared__ float sh[8192 + 64*33];

    float4 acc[4][4];
    #pragma unroll
    for (int n = 0; n < 4; ++n) {
        int row = b*HWN + n0 + ty*4 + n;
        #pragma unroll
        for (int j = 0; j < 4; ++j)
            acc[n][j] = *(const float4*)(xp + (size_t)row*DD + tx*4 + 64*j);
    }

    float inv[4];
    #pragma unroll
    for (int n = 0; n < 4; ++n) {
        int row = b*HWN + n0 + ty*4 + n;
        float s = 0.f;
        #pragma unroll
        for (int j = 0; j < 4; ++j)
            s += acc[n][j].x*acc[n][j].x + acc[n][j].y*acc[n][j].y
               + acc[n][j].z*acc[n][j].z + acc[n][j].w*acc[n][j].w;
        #pragma unroll
        for (int o = 8; o; o >>= 1) s += __shfl_xor_sync(~0u, s, o, 16);
        inv[n] = 1.0f / fmaxf(sqrtf(s), 1e-12f);
        if (tx == 0) g_inv[row] = inv[n];
    }

    float* Wn = sh;
    float* St = sh + 8192;
    for (int i = t; i < MM*DD; i += 256) Wn[i] = g_wn[i];
    __syncthreads();

    for (int m = 0; m < MM; ++m) {
        float part[4] = {0.f, 0.f, 0.f, 0.f};
        #pragma unroll
        for (int j = 0; j < 4; ++j) {
            float4 wv = *(float4*)(Wn + m*DD + tx*4 + 64*j);
            #pragma unroll
            for (int n = 0; n < 4; ++n)
                part[n] += acc[n][j].x*wv.x + acc[n][j].y*wv.y
                         + acc[n][j].z*wv.z + acc[n][j].w*wv.w;
        }
        #pragma unroll
        for (int n = 0; n < 4; ++n) {
            #pragma unroll
            for (int o = 8; o; o >>= 1)
                part[n] += __shfl_xor_sync(~0u, part[n], o, 16);
            if (tx == 0) St[(ty*4 + n)*33 + m] = part[n] * inv[n] * SCALE;
        }
    }
    __syncthreads();
    for (int i = t; i < 64*MM; i += 256) {
        int m = i >> 6, nn = i & 63;
        g_Z[(size_t)(b*MM + m)*HWN + n0 + nn] = St[nn*33 + m];
    }
}

// ------------------------------------------------------------------
__global__ __launch_bounds__(256) void k2a() {
    int bm = blockIdx.x;
    int b  = bm >> 5;
    const float* z  = g_Z + (size_t)bm * HWN;
    const float* vv = g_v + b * HWN;
    int t = threadIdx.x;

    float vals[16];
    float mx = -1e30f;
    #pragma unroll
    for (int i = 0; i < 16; ++i) {
        int idx = t + i*256;
        vals[i] = z[idx] + vv[idx];
        mx = fmaxf(mx, vals[i]);
    }
    __shared__ float red[8];
    #pragma unroll
    for (int o = 16; o; o >>= 1) mx = fmaxf(mx, __shfl_xor_sync(~0u, mx, o));
    if ((t & 31) == 0) red[t >> 5] = mx;
    __syncthreads();
    if (t < 8) {
        float r = red[t];
        #pragma unroll
        for (int o = 4; o; o >>= 1) r = fmaxf(r, __shfl_xor_sync(0xff, r, o, 8));
        if (t == 0) red[0] = r;
    }
    __syncthreads();
    mx = red[0];
    __syncthreads();

    float s = 0.f;
    #pragma unroll
    for (int i = 0; i < 16; ++i) s += expf(vals[i] - mx);
    #pragma unroll
    for (int o = 16; o; o >>= 1) s += __shfl_xor_sync(~0u, s, o);
    if ((t & 31) == 0) red[t >> 5] = s;
    __syncthreads();
    if (t == 0) {
        float tot = 0.f;
        #pragma unroll
        for (int i = 0; i < 8; ++i) tot += red[i];
        g_u[bm] = NORMC - (mx + logf(tot));
    }
}

__global__ __launch_bounds__(256) void k2b() {
    int gid = blockIdx.x*256 + threadIdx.x;
    int b = gid >> 12;
    int n = gid & (HWN - 1);
    __shared__ float us[MM];
    if (threadIdx.x < MM) us[threadIdx.x] = g_u[b*MM + threadIdx.x];
    __syncthreads();
    float vals[MM];
    float mx = -1e30f;
    #pragma unroll
    for (int m = 0; m < MM; ++m) {
        vals[m] = g_Z[(size_t)(b*MM + m)*HWN + n] + us[m];
        mx = fmaxf(mx, vals[m]);
    }
    float s = 0.f;
    #pragma unroll
    for (int m = 0; m < MM; ++m) s += expf(vals[m] - mx);
    g_v[gid] = NORMC - (mx + logf(s));
}

// ------------------------------------------------------------------
__global__ __launch_bounds__(256) void k3(const float* __restrict__ xp,
                                          float* __restrict__ vt) {
    int b  = blockIdx.y;
    int n0 = blockIdx.x * 256;
    int t  = threadIdx.x;
    __shared__ float sw[64*36];
    __shared__ float us[MM];
    if (t < MM) us[t] = g_u[b*MM + t];
    float acc[MM];
    #pragma unroll
    for (int m = 0; m < MM; ++m) acc[m] = 0.f;
    __syncthreads();

    for (int sub = 0; sub < 4; ++sub) {
        int ns = n0 + sub*64;
        __syncthreads();
        #pragma unroll
        for (int p = 0; p < 8; ++p) {
            int idx = t + p*256;
            int m = idx >> 6, nn = idx & 63;
            float zv = g_Z[(size_t)(b*MM + m)*HWN + ns + nn];
            sw[nn*36 + m] = expf(zv + us[m] + g_v[b*HWN + ns + nn] - NORMC);
        }
        __syncthreads();
        #pragma unroll 4
        for (int nn = 0; nn < 64; ++nn) {
            float xv = xp[(size_t)(b*HWN + ns + nn)*DD + t]
                     * g_inv[b*HWN + ns + nn];
            #pragma unroll
            for (int m4 = 0; m4 < 8; ++m4) {
                float4 w4 = *(float4*)(sw + nn*36 + m4*4);
                acc[m4*4+0] += xv * w4.x;
                acc[m4*4+1] += xv * w4.y;
                acc[m4*4+2] += xv * w4.z;
                acc[m4*4+3] += xv * w4.w;
            }
        }
    }
    #pragma unroll
    for (int m = 0; m < MM; ++m)
        atomicAdd(&vt[(size_t)(b*MM + m)*DD + t], acc[m]);
}

// ------------------------------------------------------------------
extern "C" void kernel_launch(void* const* d_in, const int* in_sizes, int n_in,
                              void* d_out, int out_size) {
    (void)in_sizes; (void)n_in; (void)out_size;
    const float* x    = (const float*)d_in[0];   // [16,768,64,64]
    const float* W    = (const float*)d_in[1];   // [256,768]
    const float* bias = (const float*)d_in[2];   // [256]
    const float* v    = (const float*)d_in[3];   // [32,256]

    float* out = (float*)d_out;
    float* vt  = out;                 // v_tilde [16,32,256]
    float* xp  = out + VT_ELEMS;      // x_proj  [16,4096,256]

    cudaFuncSetAttribute(k1_mma, cudaFuncAttributeMaxDynamicSharedMemorySize, SMEM_SZ);

    k_init<<<512, 256>>>(vt);
    k_wnorm<<<32, 256>>>(v);
    k_wsplit<<<384, 256>>>(W);
    k1_mma<<<dim3(32, 32), 256, SMEM_SZ>>>(x, bias, xp);
    k1b<<<dim3(64, 16), 256>>>(xp);
    for (int it = 0; it < 3; ++it) {
        k2a<<<512, 256>>>();
        k2b<<<256, 256>>>();
    }
    k3<<<dim3(16, 16), 256>>>(xp, vt);
}

// round 9
// speedup vs baseline: 1.4014x; 1.4014x over previous
#include <cuda_runtime.h>
#include <cuda_fp16.h>
#include <cstdint>
#include <math.h>

#define BB 16
#define CC 768
#define HWN 4096
#define DD 256
#define MM 32
#define SCALE 20.0f            // 1/EPS
#define NORMC (-8.32554830f)   // -log(32+4096)
#define VT_ELEMS (BB*MM*DD)

// ---- scratch (device globals; no allocations allowed) ----
__device__ float g_Z[BB*MM*HWN];     // 8 MB: Z[b,m,n]
__device__ float g_inv[BB*HWN];
__device__ float g_u[BB*MM];
__device__ float g_v[BB*HWN];
__device__ float g_wn[MM*DD];
__device__ float g_s[BB*MM];         // per-(b,m) sum of exp(Z-20)
// W as fp16 per-lane mma A-fragments: [dtile 16][ktile 48][lane 32][4 words]
__device__ __align__(16) unsigned g_wf[98304];

__device__ __forceinline__ uint32_t smem_u32(const void* p) {
    uint32_t a;
    asm("{ .reg .u64 t; cvta.to.shared.u64 t, %1; cvt.u32.u64 %0, t; }" : "=r"(a) : "l"(p));
    return a;
}
__device__ __forceinline__ unsigned pack2h(float a, float b) {
    __half ha = __float2half_rn(a), hb = __float2half_rn(b);
    return (unsigned)__half_as_ushort(ha) | ((unsigned)__half_as_ushort(hb) << 16);
}

#define LDSM_T(r0,r1,r2,r3,addr) \
    asm volatile("ldmatrix.sync.aligned.m8n8.x4.trans.shared.b16 {%0,%1,%2,%3}, [%4];" \
        : "=r"(r0), "=r"(r1), "=r"(r2), "=r"(r3) : "r"(addr))

#define MMA_F16(acc, a, b0v, b1v) \
    asm volatile("mma.sync.aligned.m16n8k16.row.col.f32.f16.f16.f32 " \
        "{%0,%1,%2,%3}, {%4,%5,%6,%7}, {%8,%9}, {%0,%1,%2,%3};" \
        : "+f"((acc)[0]), "+f"((acc)[1]), "+f"((acc)[2]), "+f"((acc)[3]) \
        : "r"((a).x), "r"((a).y), "r"((a).z), "r"((a).w), "r"(b0v), "r"(b1v))

// ------------------------------------------------------------------
// k_pre: blocks [0,32) wnorm ; [32,416) wsplit ; [416,928) init vt/g_s
__global__ __launch_bounds__(256) void k_pre(const float* __restrict__ v,
                                             const float* __restrict__ W,
                                             float* __restrict__ vt) {
    const int bx = blockIdx.x, t = threadIdx.x;
    if (bx < 32) {
        int r = bx;
        float val = v[r*DD + t];
        float s = val * val;
        #pragma unroll
        for (int o = 16; o; o >>= 1) s += __shfl_xor_sync(~0u, s, o);
        __shared__ float red[8];
        if ((t & 31) == 0) red[t >> 5] = s;
        __syncthreads();
        if (t < 8) {
            float r2 = red[t];
            #pragma unroll
            for (int o = 4; o; o >>= 1) r2 += __shfl_xor_sync(0xff, r2, o, 8);
            if (t == 0) red[0] = r2;
        }
        __syncthreads();
        float inv = 1.0f / fmaxf(sqrtf(red[0]), 1e-12f);
        g_wn[r*DD + t] = val * inv;
    } else if (bx < 416) {
        int gid = (bx - 32)*256 + t;     // 0..98303
        int w = gid & 3, lane = (gid >> 2) & 31, tile = gid >> 7;
        int kt = tile % 48, dt = tile / 48;
        int d = dt*16 + (lane >> 2) + (w & 1)*8;
        int c = kt*16 + (lane & 3)*2 + (w >> 1)*8;
        g_wf[gid] = pack2h(W[(size_t)d*CC + c], W[(size_t)d*CC + c + 1]);
    } else {
        int i = (bx - 416)*256 + t;      // 0..131071
        vt[i] = 0.0f;
        if (i < BB*MM) g_s[i] = 0.0f;
    }
}

// ------------------------------------------------------------------
// k1_mma: x_proj[b,n,d] = W x + bias via pure fp16 mma.sync (fp32 accum).
// CTA: 128 d x 128 n, 256 threads (8 warps), 2 CTAs/SM. 32-k chunks.
#define XPITCH 304                      // smem row pitch (bytes)
#define XBUF   9728                     // one x buffer (32 rows)
#define EP_OFF 19456                    // epilogue staging region
#define EPITCH 132                      // epilogue float pitch
#define SMEM_SZ (EP_OFF + 64*EPITCH*4)  // 53248

__global__ __launch_bounds__(256, 2) void k1_mma(const float* __restrict__ x,
                                                 const float* __restrict__ bias,
                                                 float* __restrict__ xp) {
    extern __shared__ char smc[];
    const uint32_t sb = smem_u32(smc);
    const int b = blockIdx.y >> 1, dh = blockIdx.y & 1;
    const int n0 = blockIdx.x * 128;
    const int t = threadIdx.x, w = t >> 5, lane = t & 31;
    const int nw = (w >> 2) * 64;

    float acc[2][8][4];
    #pragma unroll
    for (int mt = 0; mt < 2; ++mt)
        #pragma unroll
        for (int nt = 0; nt < 8; ++nt)
            #pragma unroll
            for (int i = 0; i < 4; ++i) acc[mt][nt][i] = 0.f;

    const float* xb = x + (size_t)b * CC * HWN + n0;
    const int c0 = t >> 5;              // base row 0..7 (rows c0+8i)
    const int n4 = t & 31;

    float4 vr[4];
    #pragma unroll
    for (int i = 0; i < 4; ++i)
        vr[i] = *(const float4*)(xb + (size_t)(c0 + 8*i)*HWN + n4*4);

    int buf = 0;
    for (int kc = 0; kc < CC; kc += 32, buf ^= 1) {
        // STS prefetched 32-row chunk (fp16 packed)
        {
            char* base = smc + buf*XBUF;
            #pragma unroll
            for (int i = 0; i < 4; ++i) {
                unsigned p01 = pack2h(vr[i].x, vr[i].y);
                unsigned p23 = pack2h(vr[i].z, vr[i].w);
                *(uint2*)(base + (c0 + 8*i)*XPITCH + n4*8) = make_uint2(p01, p23);
            }
        }
        // A-fragments for this chunk (gmem/L2, independent of barrier)
        uint4 ah[2][2];
        #pragma unroll
        for (int ks = 0; ks < 2; ++ks)
            #pragma unroll
            for (int mt = 0; mt < 2; ++mt) {
                int dt = dh*8 + (w & 3)*2 + mt;
                int kt = (kc >> 4) + ks;
                ah[ks][mt] = *(const uint4*)(g_wf + ((dt*48 + kt)*32 + lane)*4);
            }
        // prefetch next chunk
        if (kc + 32 < CC) {
            #pragma unroll
            for (int i = 0; i < 4; ++i)
                vr[i] = *(const float4*)(xb + (size_t)(kc + 32 + c0 + 8*i)*HWN + n4*4);
        }
        __syncthreads();

        const uint32_t sxb = sb + buf*XBUF;
        #pragma unroll
        for (int ks = 0; ks < 2; ++ks) {
            #pragma unroll
            for (int j = 0; j < 4; ++j) {
                uint32_t baddr = sxb + (uint32_t)((ks*16 + (lane & 15))*XPITCH
                               + (nw + j*16 + ((lane >> 4) << 3))*2);
                unsigned b0,b1,b2,b3;
                LDSM_T(b0,b1,b2,b3, baddr);
                #pragma unroll
                for (int mt = 0; mt < 2; ++mt) {
                    MMA_F16(acc[mt][2*j],   ah[ks][mt], b0, b1);
                    MMA_F16(acc[mt][2*j+1], ah[ks][mt], b2, b3);
                }
            }
        }
        // next STS targets other buffer; safe without trailing sync
    }

    // epilogue: stage per 64-n half for coalesced stores of 128 d
    float* s_ep = (float*)(smc + EP_OFF);
    const float4* bias4 = (const float4*)bias;
    #pragma unroll
    for (int p = 0; p < 2; ++p) {
        __syncthreads();
        if ((w >> 2) == p) {
            #pragma unroll
            for (int mt = 0; mt < 2; ++mt) {
                int d = (w & 3)*32 + mt*16 + (lane >> 2);
                #pragma unroll
                for (int nt = 0; nt < 8; ++nt) {
                    int nl = nt*8 + (lane & 3)*2;
                    s_ep[nl*EPITCH + d]           = acc[mt][nt][0];
                    s_ep[(nl+1)*EPITCH + d]       = acc[mt][nt][1];
                    s_ep[nl*EPITCH + d + 8]       = acc[mt][nt][2];
                    s_ep[(nl+1)*EPITCH + d + 8]   = acc[mt][nt][3];
                }
            }
        }
        __syncthreads();
        #pragma unroll
        for (int i = 0; i < 8; ++i) {
            int idx = t + i*256;
            int row = idx >> 5, c4 = idx & 31;
            float4 v = *(float4*)(s_ep + row*EPITCH + c4*4);
            float4 bv = bias4[dh*32 + c4];
            v.x += bv.x; v.y += bv.y; v.z += bv.z; v.w += bv.w;
            *(float4*)(xp + (size_t)(b*HWN + n0 + p*64 + row)*DD + dh*128 + c4*4) = v;
        }
    }
}

// ------------------------------------------------------------------
// k1b: row L2 norms + cluster scores -> Z ; also accumulates
// g_s[b,m] += sum_n exp(Z-20) so iteration-1's u comes for free.
__global__ __launch_bounds__(256) void k1b(const float* __restrict__ xp) {
    const int b = blockIdx.y, n0 = blockIdx.x * 64;
    const int t = threadIdx.x, tx = t & 15, ty = t >> 4;
    __shared__ float sh[8192 + 64*33];

    float4 acc[4][4];
    #pragma unroll
    for (int n = 0; n < 4; ++n) {
        int row = b*HWN + n0 + ty*4 + n;
        #pragma unroll
        for (int j = 0; j < 4; ++j)
            acc[n][j] = *(const float4*)(xp + (size_t)row*DD + tx*4 + 64*j);
    }

    float inv[4];
    #pragma unroll
    for (int n = 0; n < 4; ++n) {
        int row = b*HWN + n0 + ty*4 + n;
        float s = 0.f;
        #pragma unroll
        for (int j = 0; j < 4; ++j)
            s += acc[n][j].x*acc[n][j].x + acc[n][j].y*acc[n][j].y
               + acc[n][j].z*acc[n][j].z + acc[n][j].w*acc[n][j].w;
        #pragma unroll
        for (int o = 8; o; o >>= 1) s += __shfl_xor_sync(~0u, s, o, 16);
        inv[n] = 1.0f / fmaxf(sqrtf(s), 1e-12f);
        if (tx == 0) g_inv[row] = inv[n];
    }

    float* Wn = sh;
    float* St = sh + 8192;
    for (int i = t; i < MM*DD; i += 256) Wn[i] = g_wn[i];
    __syncthreads();

    for (int m = 0; m < MM; ++m) {
        float part[4] = {0.f, 0.f, 0.f, 0.f};
        #pragma unroll
        for (int j = 0; j < 4; ++j) {
            float4 wv = *(float4*)(Wn + m*DD + tx*4 + 64*j);
            #pragma unroll
            for (int n = 0; n < 4; ++n)
                part[n] += acc[n][j].x*wv.x + acc[n][j].y*wv.y
                         + acc[n][j].z*wv.z + acc[n][j].w*wv.w;
        }
        #pragma unroll
        for (int n = 0; n < 4; ++n) {
            #pragma unroll
            for (int o = 8; o; o >>= 1)
                part[n] += __shfl_xor_sync(~0u, part[n], o, 16);
            if (tx == 0) St[(ty*4 + n)*33 + m] = part[n] * inv[n] * SCALE;
        }
    }
    __syncthreads();
    // store Z coalesced along n
    for (int i = t; i < 64*MM; i += 256) {
        int m = i >> 6, nn = i & 63;
        g_Z[(size_t)(b*MM + m)*HWN + n0 + nn] = St[nn*33 + m];
    }
    // partial sums of exp(Z - 20) per m (Z <= 20 since |score| <= 1)
    {
        int m = t & 31, g = t >> 5;          // 8 groups of nn
        float ps = 0.f;
        #pragma unroll
        for (int j = 0; j < 8; ++j)
            ps += expf(St[(g*8 + j)*33 + m] - 20.0f);
        sh[m*9 + g] = ps;                     // reuse Wn region (done with it)
    }
    __syncthreads();
    if (t < 32) {
        float s = 0.f;
        #pragma unroll
        for (int g = 0; g < 8; ++g) s += sh[t*9 + g];
        atomicAdd(&g_s[b*MM + t], s);
    }
}

// ------------------------------------------------------------------
// u[b,m] = norm - lse_n(Z[b,m,:] + v[b,:]) ; one block per (b,m)
__global__ __launch_bounds__(256) void k2a() {
    int bm = blockIdx.x;
    int b  = bm >> 5;
    const float* z  = g_Z + (size_t)bm * HWN;
    const float* vv = g_v + b * HWN;
    int t = threadIdx.x;

    float vals[16];
    float mx = -1e30f;
    #pragma unroll
    for (int i = 0; i < 16; ++i) {
        int idx = t + i*256;
        vals[i] = z[idx] + vv[idx];
        mx = fmaxf(mx, vals[i]);
    }
    __shared__ float red[8];
    #pragma unroll
    for (int o = 16; o; o >>= 1) mx = fmaxf(mx, __shfl_xor_sync(~0u, mx, o));
    if ((t & 31) == 0) red[t >> 5] = mx;
    __syncthreads();
    if (t < 8) {
        float r = red[t];
        #pragma unroll
        for (int o = 4; o; o >>= 1) r = fmaxf(r, __shfl_xor_sync(0xff, r, o, 8));
        if (t == 0) red[0] = r;
    }
    __syncthreads();
    mx = red[0];
    __syncthreads();

    float s = 0.f;
    #pragma unroll
    for (int i = 0; i < 16; ++i) s += expf(vals[i] - mx);
    #pragma unroll
    for (int o = 16; o; o >>= 1) s += __shfl_xor_sync(~0u, s, o);
    if ((t & 31) == 0) red[t >> 5] = s;
    __syncthreads();
    if (t == 0) {
        float tot = 0.f;
        #pragma unroll
        for (int i = 0; i < 8; ++i) tot += red[i];
        g_u[bm] = NORMC - (mx + logf(tot));
    }
}

// v[b,n] = norm - lse_m(Z[b,:,n] + u[b,:]) ; one thread per (b,n)
// first=1: u comes from g_s (iteration-1 u computed inline)
__global__ __launch_bounds__(256) void k2b(int first) {
    int gid = blockIdx.x*256 + threadIdx.x;
    int b = gid >> 12;
    int n = gid & (HWN - 1);
    __shared__ float us[MM];
    if (threadIdx.x < MM) {
        us[threadIdx.x] = first
            ? NORMC - (20.0f + logf(g_s[b*MM + threadIdx.x]))
            : g_u[b*MM + threadIdx.x];
    }
    __syncthreads();
    float vals[MM];
    float mx = -1e30f;
    #pragma unroll
    for (int m = 0; m < MM; ++m) {
        vals[m] = g_Z[(size_t)(b*MM + m)*HWN + n] + us[m];
        mx = fmaxf(mx, vals[m]);
    }
    float s = 0.f;
    #pragma unroll
    for (int m = 0; m < MM; ++m) s += expf(vals[m] - mx);
    g_v[gid] = NORMC - (mx + logf(s));
}

// ------------------------------------------------------------------
// k3: computes final v inline (column softmax), then
// v_tilde[b,m,d] += sum_n xf[b,n,d] * weight[m,n]
// Block (b, 256-n chunk); softmax phase: thread = nn; GEMM phase: thread = d.
__global__ __launch_bounds__(256) void k3(const float* __restrict__ xp,
                                          float* __restrict__ vt) {
    int b  = blockIdx.y;
    int n0 = blockIdx.x * 256;
    int t  = threadIdx.x;
    __shared__ float sw[256*36];         // weights [nn][m], pitch 36
    __shared__ float us[MM];
    __shared__ float sinv[256];
    if (t < MM) us[t] = g_u[b*MM + t];
    sinv[t] = g_inv[b*HWN + n0 + t];
    __syncthreads();

    // softmax over m for column n0+t (= Z + u, final v folded in)
    {
        int n = n0 + t;
        float vals[MM];
        float mx = -1e30f;
        #pragma unroll
        for (int m = 0; m < MM; ++m) {
            vals[m] = g_Z[(size_t)(b*MM + m)*HWN + n] + us[m];
            mx = fmaxf(mx, vals[m]);
        }
        float s = 0.f;
        #pragma unroll
        for (int m = 0; m < MM; ++m) {
            vals[m] = expf(vals[m] - mx);
            s += vals[m];
        }
        float is = 1.0f / s;
        #pragma unroll
        for (int m = 0; m < MM; ++m) sw[t*36 + m] = vals[m] * is;
    }
    __syncthreads();

    float acc[MM];
    #pragma unroll
    for (int m = 0; m < MM; ++m) acc[m] = 0.f;

    for (int nn = 0; nn < 256; ++nn) {
        float xv = xp[(size_t)(b*HWN + n0 + nn)*DD + t] * sinv[nn];
        #pragma unroll
        for (int m4 = 0; m4 < 8; ++m4) {
            float4 w4 = *(float4*)(sw + nn*36 + m4*4);
            acc[m4*4+0] += xv * w4.x;
            acc[m4*4+1] += xv * w4.y;
            acc[m4*4+2] += xv * w4.z;
            acc[m4*4+3] += xv * w4.w;
        }
    }
    #pragma unroll
    for (int m = 0; m < MM; ++m)
        atomicAdd(&vt[(size_t)(b*MM + m)*DD + t], acc[m]);
}

// ------------------------------------------------------------------
extern "C" void kernel_launch(void* const* d_in, const int* in_sizes, int n_in,
                              void* d_out, int out_size) {
    (void)in_sizes; (void)n_in; (void)out_size;
    const float* x    = (const float*)d_in[0];   // [16,768,64,64]
    const float* W    = (const float*)d_in[1];   // [256,768]
    const float* bias = (const float*)d_in[2];   // [256]
    const float* v    = (const float*)d_in[3];   // [32,256]

    float* out = (float*)d_out;
    float* vt  = out;                 // v_tilde [16,32,256]
    float* xp  = out + VT_ELEMS;      // x_proj  [16,4096,256]

    cudaFuncSetAttribute(k1_mma, cudaFuncAttributeMaxDynamicSharedMemorySize, SMEM_SZ);

    k_pre<<<928, 256>>>(v, W, vt);
    k1_mma<<<dim3(32, 32), 256, SMEM_SZ>>>(x, bias, xp);
    k1b<<<dim3(64, 16), 256>>>(xp);
    // Sinkhorn: u1 folded into k1b sums; v3 folded into k3
    k2b<<<256, 256>>>(1);     // v1 (u1 from g_s)
    k2a<<<512, 256>>>();      // u2
    k2b<<<256, 256>>>(0);     // v2
    k2a<<<512, 256>>>();      // u3
    k3<<<dim3(16, 16), 256>>>(xp, vt);   // v3 inline + aggregation
}

// round 10
// speedup vs baseline: 1.8377x; 1.3113x over previous
#include <cuda_runtime.h>
#include <cuda_fp16.h>
#include <cstdint>
#include <math.h>

#define BB 16
#define CC 768
#define HWN 4096
#define DD 256
#define MM 32
#define SCALE 20.0f            // 1/EPS
#define NORMC (-8.32554830f)   // -log(32+4096)
#define VT_ELEMS (BB*MM*DD)

// ---- scratch (device globals; no allocations allowed) ----
__device__ float g_Z[BB*MM*HWN];     // 8 MB: RAW scores x_proj . wn  [b,m,n]
__device__ float g_nrm[BB*HWN];      // per-row sum of squares of x_proj
__device__ float g_u[BB*MM];
__device__ float g_v[BB*HWN];
__device__ float g_wn[MM*DD];
// W as fp16 per-lane mma A-fragments: [dtile 16][ktile 48][lane 32][4 words]
__device__ __align__(16) unsigned g_wf[98304];

__device__ __forceinline__ uint32_t smem_u32(const void* p) {
    uint32_t a;
    asm("{ .reg .u64 t; cvta.to.shared.u64 t, %1; cvt.u32.u64 %0, t; }" : "=r"(a) : "l"(p));
    return a;
}
__device__ __forceinline__ unsigned pack2h(float a, float b) {
    __half ha = __float2half_rn(a), hb = __float2half_rn(b);
    return (unsigned)__half_as_ushort(ha) | ((unsigned)__half_as_ushort(hb) << 16);
}
__device__ __forceinline__ float inv_from_nrm(float nv) {
    return rsqrtf(fmaxf(nv, 1e-24f));   // == 1/max(sqrt(nv),1e-12)
}

#define LDSM_T(r0,r1,r2,r3,addr) \
    asm volatile("ldmatrix.sync.aligned.m8n8.x4.trans.shared.b16 {%0,%1,%2,%3}, [%4];" \
        : "=r"(r0), "=r"(r1), "=r"(r2), "=r"(r3) : "r"(addr))

#define MMA_F16(acc, a, b0v, b1v) \
    asm volatile("mma.sync.aligned.m16n8k16.row.col.f32.f16.f16.f32 " \
        "{%0,%1,%2,%3}, {%4,%5,%6,%7}, {%8,%9}, {%0,%1,%2,%3};" \
        : "+f"((acc)[0]), "+f"((acc)[1]), "+f"((acc)[2]), "+f"((acc)[3]) \
        : "r"((a).x), "r"((a).y), "r"((a).z), "r"((a).w), "r"(b0v), "r"(b1v))

// ------------------------------------------------------------------
// k_pre: [0,32) wnorm ; [32,416) wsplit ; [416,544) zero vt ;
//        [544,608) zero g_nrm ; [608,2656) zero g_Z
__global__ __launch_bounds__(256) void k_pre(const float* __restrict__ v,
                                             const float* __restrict__ W,
                                             float* __restrict__ vt) {
    const int bx = blockIdx.x, t = threadIdx.x;
    if (bx < 32) {
        int r = bx;
        float val = v[r*DD + t];
        float s = val * val;
        #pragma unroll
        for (int o = 16; o; o >>= 1) s += __shfl_xor_sync(~0u, s, o);
        __shared__ float red[8];
        if ((t & 31) == 0) red[t >> 5] = s;
        __syncthreads();
        if (t < 8) {
            float r2 = red[t];
            #pragma unroll
            for (int o = 4; o; o >>= 1) r2 += __shfl_xor_sync(0xff, r2, o, 8);
            if (t == 0) red[0] = r2;
        }
        __syncthreads();
        float inv = 1.0f / fmaxf(sqrtf(red[0]), 1e-12f);
        g_wn[r*DD + t] = val * inv;
    } else if (bx < 416) {
        int gid = (bx - 32)*256 + t;
        int w = gid & 3, lane = (gid >> 2) & 31, tile = gid >> 7;
        int kt = tile % 48, dt = tile / 48;
        int d = dt*16 + (lane >> 2) + (w & 1)*8;
        int c = kt*16 + (lane & 3)*2 + (w >> 1)*8;
        g_wf[gid] = pack2h(W[(size_t)d*CC + c], W[(size_t)d*CC + c + 1]);
    } else if (bx < 544) {
        ((float4*)vt)[(bx - 416)*256 + t] = make_float4(0.f,0.f,0.f,0.f);
    } else if (bx < 608) {
        ((float4*)g_nrm)[(bx - 544)*256 + t] = make_float4(0.f,0.f,0.f,0.f);
    } else {
        ((float4*)g_Z)[(bx - 608)*256 + t] = make_float4(0.f,0.f,0.f,0.f);
    }
}

// ------------------------------------------------------------------
// k1_mma: fp16 mma GEMM + bias + xp store + fused norms & raw scores.
// CTA: 128 d x 128 n (dh half of d), 256 threads, 2 CTAs/SM.
#define XPITCH 304
#define XBUF   9728                     // one x buffer (32 rows fp16)
#define EP_OFF 19456                    // x_proj staging [64 n][132 pitch]
#define EPITCH 132
#define WN_OFF (EP_OFF + 64*EPITCH*4)   // 53248 ; wn half [32 m][132 pitch]
#define WPITCH 132
#define SMEM_SZ (WN_OFF + 32*WPITCH*4)  // 70144

__global__ __launch_bounds__(256, 2) void k1_mma(const float* __restrict__ x,
                                                 const float* __restrict__ bias,
                                                 float* __restrict__ xp) {
    extern __shared__ char smc[];
    const uint32_t sb = smem_u32(smc);
    const int b = blockIdx.y >> 1, dh = blockIdx.y & 1;
    const int n0 = blockIdx.x * 128;
    const int t = threadIdx.x, w = t >> 5, lane = t & 31;
    const int nw = (w >> 2) * 64;

    float acc[2][8][4];
    #pragma unroll
    for (int mt = 0; mt < 2; ++mt)
        #pragma unroll
        for (int nt = 0; nt < 8; ++nt)
            #pragma unroll
            for (int i = 0; i < 4; ++i) acc[mt][nt][i] = 0.f;

    // stage this CTA's half of normalized cluster weights into smem
    float* wn_s = (float*)(smc + WN_OFF);
    #pragma unroll
    for (int i = 0; i < 16; ++i) {
        int idx = t + i*256;             // 0..4095
        int m = idx >> 7, dl = idx & 127;
        wn_s[m*WPITCH + dl] = g_wn[m*DD + dh*128 + dl];
    }

    const float* xb = x + (size_t)b * CC * HWN + n0;
    const int c0 = t >> 5;
    const int n4 = t & 31;

    float4 vr[4];
    #pragma unroll
    for (int i = 0; i < 4; ++i)
        vr[i] = *(const float4*)(xb + (size_t)(c0 + 8*i)*HWN + n4*4);

    int buf = 0;
    for (int kc = 0; kc < CC; kc += 32, buf ^= 1) {
        {
            char* base = smc + buf*XBUF;
            #pragma unroll
            for (int i = 0; i < 4; ++i) {
                unsigned p01 = pack2h(vr[i].x, vr[i].y);
                unsigned p23 = pack2h(vr[i].z, vr[i].w);
                *(uint2*)(base + (c0 + 8*i)*XPITCH + n4*8) = make_uint2(p01, p23);
            }
        }
        uint4 ah[2][2];
        #pragma unroll
        for (int ks = 0; ks < 2; ++ks)
            #pragma unroll
            for (int mt = 0; mt < 2; ++mt) {
                int dt = dh*8 + (w & 3)*2 + mt;
                int kt = (kc >> 4) + ks;
                ah[ks][mt] = *(const uint4*)(g_wf + ((dt*48 + kt)*32 + lane)*4);
            }
        if (kc + 32 < CC) {
            #pragma unroll
            for (int i = 0; i < 4; ++i)
                vr[i] = *(const float4*)(xb + (size_t)(kc + 32 + c0 + 8*i)*HWN + n4*4);
        }
        __syncthreads();

        const uint32_t sxb = sb + buf*XBUF;
        #pragma unroll
        for (int ks = 0; ks < 2; ++ks) {
            #pragma unroll
            for (int j = 0; j < 4; ++j) {
                uint32_t baddr = sxb + (uint32_t)((ks*16 + (lane & 15))*XPITCH
                               + (nw + j*16 + ((lane >> 4) << 3))*2);
                unsigned b0,b1,b2,b3;
                LDSM_T(b0,b1,b2,b3, baddr);
                #pragma unroll
                for (int mt = 0; mt < 2; ++mt) {
                    MMA_F16(acc[mt][2*j],   ah[ks][mt], b0, b1);
                    MMA_F16(acc[mt][2*j+1], ah[ks][mt], b2, b3);
                }
            }
        }
    }

    // bias values for this thread's output columns
    const int dbase = (w & 3)*32 + (lane >> 2);
    float bj[2][2];
    #pragma unroll
    for (int mt = 0; mt < 2; ++mt) {
        bj[mt][0] = bias[dh*128 + dbase + mt*16];
        bj[mt][1] = bias[dh*128 + dbase + mt*16 + 8];
    }

    // epilogue per 64-n half: stage x_proj (+bias), store, norms, scores
    float* s_ep = (float*)(smc + EP_OFF);
    #pragma unroll
    for (int p = 0; p < 2; ++p) {
        __syncthreads();
        if ((w >> 2) == p) {
            #pragma unroll
            for (int mt = 0; mt < 2; ++mt) {
                int d = (w & 3)*32 + mt*16 + (lane >> 2);
                #pragma unroll
                for (int nt = 0; nt < 8; ++nt) {
                    int nl = nt*8 + (lane & 3)*2;
                    s_ep[nl*EPITCH + d]           = acc[mt][nt][0] + bj[mt][0];
                    s_ep[(nl+1)*EPITCH + d]       = acc[mt][nt][1] + bj[mt][0];
                    s_ep[nl*EPITCH + d + 8]       = acc[mt][nt][2] + bj[mt][1];
                    s_ep[(nl+1)*EPITCH + d + 8]   = acc[mt][nt][3] + bj[mt][1];
                }
            }
        }
        __syncthreads();
        // store x_proj
        #pragma unroll
        for (int i = 0; i < 8; ++i) {
            int idx = t + i*256;
            int row = idx >> 5, c4 = idx & 31;
            float4 v = *(float4*)(s_ep + row*EPITCH + c4*4);
            *(float4*)(xp + (size_t)(b*HWN + n0 + p*64 + row)*DD + dh*128 + c4*4) = v;
        }
        const int n = t >> 2, q = t & 3;
        const int gn = n0 + p*64 + n;
        // partial row norms (this CTA's 128 d)
        {
            float s = 0.f;
            #pragma unroll
            for (int k = 0; k < 8; ++k) {
                float4 xv = *(float4*)(s_ep + n*EPITCH + q*32 + k*4);
                s += xv.x*xv.x + xv.y*xv.y + xv.z*xv.z + xv.w*xv.w;
            }
            s += __shfl_xor_sync(~0u, s, 1, 4);
            s += __shfl_xor_sync(~0u, s, 2, 4);
            if (q == 0) atomicAdd(&g_nrm[b*HWN + gn], s);
        }
        // partial raw scores: thread handles n, m = q + 4j
        {
            float a8[8];
            #pragma unroll
            for (int j = 0; j < 8; ++j) a8[j] = 0.f;
            #pragma unroll 4
            for (int d4 = 0; d4 < 32; ++d4) {
                float4 xv = *(float4*)(s_ep + n*EPITCH + d4*4);
                #pragma unroll
                for (int j = 0; j < 8; ++j) {
                    float4 w4 = *(float4*)(wn_s + (q + 4*j)*WPITCH + d4*4);
                    a8[j] += xv.x*w4.x + xv.y*w4.y + xv.z*w4.z + xv.w*w4.w;
                }
            }
            #pragma unroll
            for (int j = 0; j < 8; ++j)
                atomicAdd(&g_Z[(size_t)(b*MM + q + 4*j)*HWN + gn], a8[j]);
        }
    }
}

// ------------------------------------------------------------------
// u[b,m] = NORMC - lse_n(Zs + v) ; Zs = rawZ * inv(nrm) * SCALE
__global__ __launch_bounds__(256) void k2a(int first) {
    int bm = blockIdx.x;
    int b  = bm >> 5;
    const float* z  = g_Z + (size_t)bm * HWN;
    const float* nr = g_nrm + b * HWN;
    const float* vv = g_v + b * HWN;
    int t = threadIdx.x;

    float vals[16];
    float mx = -1e30f;
    #pragma unroll
    for (int i = 0; i < 16; ++i) {
        int idx = t + i*256;
        float zs = z[idx] * inv_from_nrm(nr[idx]) * SCALE;
        vals[i] = first ? zs : zs + vv[idx];
        mx = fmaxf(mx, vals[i]);
    }
    __shared__ float red[8];
    #pragma unroll
    for (int o = 16; o; o >>= 1) mx = fmaxf(mx, __shfl_xor_sync(~0u, mx, o));
    if ((t & 31) == 0) red[t >> 5] = mx;
    __syncthreads();
    if (t < 8) {
        float r = red[t];
        #pragma unroll
        for (int o = 4; o; o >>= 1) r = fmaxf(r, __shfl_xor_sync(0xff, r, o, 8));
        if (t == 0) red[0] = r;
    }
    __syncthreads();
    mx = red[0];
    __syncthreads();

    float s = 0.f;
    #pragma unroll
    for (int i = 0; i < 16; ++i) s += expf(vals[i] - mx);
    #pragma unroll
    for (int o = 16; o; o >>= 1) s += __shfl_xor_sync(~0u, s, o);
    if ((t & 31) == 0) red[t >> 5] = s;
    __syncthreads();
    if (t == 0) {
        float tot = 0.f;
        #pragma unroll
        for (int i = 0; i < 8; ++i) tot += red[i];
        g_u[bm] = NORMC - (mx + logf(tot));
    }
}

// v[b,n] = NORMC - lse_m(Zs + u)
__global__ __launch_bounds__(256) void k2b() {
    int gid = blockIdx.x*256 + threadIdx.x;
    int b = gid >> 12;
    int n = gid & (HWN - 1);
    __shared__ float us[MM];
    if (threadIdx.x < MM) us[threadIdx.x] = g_u[b*MM + threadIdx.x];
    __syncthreads();
    float scal = inv_from_nrm(g_nrm[gid]) * SCALE;
    float vals[MM];
    float mx = -1e30f;
    #pragma unroll
    for (int m = 0; m < MM; ++m) {
        vals[m] = g_Z[(size_t)(b*MM + m)*HWN + n] * scal + us[m];
        mx = fmaxf(mx, vals[m]);
    }
    float s = 0.f;
    #pragma unroll
    for (int m = 0; m < MM; ++m) s += expf(vals[m] - mx);
    g_v[gid] = NORMC - (mx + logf(s));
}

// ------------------------------------------------------------------
// k3: final v inline (column softmax) + aggregation into v_tilde
__global__ __launch_bounds__(256) void k3(const float* __restrict__ xp,
                                          float* __restrict__ vt) {
    int b  = blockIdx.y;
    int n0 = blockIdx.x * 256;
    int t  = threadIdx.x;
    __shared__ float sw[256*36];
    __shared__ float us[MM];
    __shared__ float sinv[256];
    if (t < MM) us[t] = g_u[b*MM + t];
    float myinv = inv_from_nrm(g_nrm[b*HWN + n0 + t]);
    sinv[t] = myinv;
    __syncthreads();

    {
        int n = n0 + t;
        float scal = myinv * SCALE;
        float vals[MM];
        float mx = -1e30f;
        #pragma unroll
        for (int m = 0; m < MM; ++m) {
            vals[m] = g_Z[(size_t)(b*MM + m)*HWN + n] * scal + us[m];
            mx = fmaxf(mx, vals[m]);
        }
        float s = 0.f;
        #pragma unroll
        for (int m = 0; m < MM; ++m) {
            vals[m] = expf(vals[m] - mx);
            s += vals[m];
        }
        float is = 1.0f / s;
        #pragma unroll
        for (int m = 0; m < MM; ++m) sw[t*36 + m] = vals[m] * is;
    }
    __syncthreads();

    float acc[MM];
    #pragma unroll
    for (int m = 0; m < MM; ++m) acc[m] = 0.f;

    for (int nn = 0; nn < 256; ++nn) {
        float xv = xp[(size_t)(b*HWN + n0 + nn)*DD + t] * sinv[nn];
        #pragma unroll
        for (int m4 = 0; m4 < 8; ++m4) {
            float4 w4 = *(float4*)(sw + nn*36 + m4*4);
            acc[m4*4+0] += xv * w4.x;
            acc[m4*4+1] += xv * w4.y;
            acc[m4*4+2] += xv * w4.z;
            acc[m4*4+3] += xv * w4.w;
        }
    }
    #pragma unroll
    for (int m = 0; m < MM; ++m)
        atomicAdd(&vt[(size_t)(b*MM + m)*DD + t], acc[m]);
}

// ------------------------------------------------------------------
extern "C" void kernel_launch(void* const* d_in, const int* in_sizes, int n_in,
                              void* d_out, int out_size) {
    (void)in_sizes; (void)n_in; (void)out_size;
    const float* x    = (const float*)d_in[0];   // [16,768,64,64]
    const float* W    = (const float*)d_in[1];   // [256,768]
    const float* bias = (const float*)d_in[2];   // [256]
    const float* v    = (const float*)d_in[3];   // [32,256]

    float* out = (float*)d_out;
    float* vt  = out;                 // v_tilde [16,32,256]
    float* xp  = out + VT_ELEMS;      // x_proj  [16,4096,256]

    cudaFuncSetAttribute(k1_mma, cudaFuncAttributeMaxDynamicSharedMemorySize, SMEM_SZ);

    k_pre<<<2656, 256>>>(v, W, vt);
    k1_mma<<<dim3(32, 32), 256, SMEM_SZ>>>(x, bias, xp);
    k2a<<<512, 256>>>(1);     // u1 (v0 = 0)
    k2b<<<256, 256>>>();      // v1
    k2a<<<512, 256>>>(0);     // u2
    k2b<<<256, 256>>>();      // v2
    k2a<<<512, 256>>>(0);     // u3
    k3<<<dim3(16, 16), 256>>>(xp, vt);   // v3 inline + aggregation
}

// round 12
// speedup vs baseline: 1.9038x; 1.0360x over previous
#include <cuda_runtime.h>
#include <cuda_fp16.h>
#include <cstdint>
#include <math.h>

#define BB 16
#define CC 768
#define HWN 4096
#define DD 256
#define MM 32
#define SCALE 20.0f            // 1/EPS
#define NORMC (-8.32554830f)   // -log(32+4096)
#define VT_ELEMS (BB*MM*DD)

// ---- scratch (device globals; no allocations allowed) ----
__device__ float g_Z[BB*MM*HWN];     // 8 MB: RAW scores xp.wn [b,m,n]
__device__ float g_nrm[BB*HWN];      // per-row sum of squares of x_proj
__device__ float g_u[BB*MM];
__device__ float g_v[BB*HWN];
__device__ float g_wn[MM*DD];
__device__ float g_wnb[MM];          // wn . bias
// W as fp16 per-lane mma A-fragments: [dtile 16][ktile 48][lane 32][4 words]
__device__ __align__(16) unsigned g_wf[98304];
// wn.W as fp16 A-fragments: [dtile 2][ktile 48][lane 32][4 words]
__device__ __align__(16) unsigned g_wsf[12288];

__device__ __forceinline__ uint32_t smem_u32(const void* p) {
    uint32_t a;
    asm("{ .reg .u64 t; cvta.to.shared.u64 t, %1; cvt.u32.u64 %0, t; }" : "=r"(a) : "l"(p));
    return a;
}
__device__ __forceinline__ unsigned pack2h(float a, float b) {
    __half ha = __float2half_rn(a), hb = __float2half_rn(b);
    return (unsigned)__half_as_ushort(ha) | ((unsigned)__half_as_ushort(hb) << 16);
}
__device__ __forceinline__ float inv_from_nrm(float nv) {
    return rsqrtf(fmaxf(nv, 1e-24f));
}

#define LDSM_T(r0,r1,r2,r3,addr) \
    asm volatile("ldmatrix.sync.aligned.m8n8.x4.trans.shared.b16 {%0,%1,%2,%3}, [%4];" \
        : "=r"(r0), "=r"(r1), "=r"(r2), "=r"(r3) : "r"(addr))

#define MMA_F16(acc, a, b0v, b1v) \
    asm volatile("mma.sync.aligned.m16n8k16.row.col.f32.f16.f16.f32 " \
        "{%0,%1,%2,%3}, {%4,%5,%6,%7}, {%8,%9}, {%0,%1,%2,%3};" \
        : "+f"((acc)[0]), "+f"((acc)[1]), "+f"((acc)[2]), "+f"((acc)[3]) \
        : "r"((a).x), "r"((a).y), "r"((a).z), "r"((a).w), "r"(b0v), "r"(b1v))

// ------------------------------------------------------------------
// k_pre1: [0,32) wnorm ; [32,416) wsplit ; [416,544) zero vt ; [544,608) zero g_nrm
__global__ __launch_bounds__(256) void k_pre1(const float* __restrict__ v,
                                              const float* __restrict__ W,
                                              float* __restrict__ vt) {
    const int bx = blockIdx.x, t = threadIdx.x;
    if (bx < 32) {
        int r = bx;
        float val = v[r*DD + t];
        float s = val * val;
        #pragma unroll
        for (int o = 16; o; o >>= 1) s += __shfl_xor_sync(~0u, s, o);
        __shared__ float red[8];
        if ((t & 31) == 0) red[t >> 5] = s;
        __syncthreads();
        if (t < 8) {
            float r2 = red[t];
            #pragma unroll
            for (int o = 4; o; o >>= 1) r2 += __shfl_xor_sync(0xff, r2, o, 8);
            if (t == 0) red[0] = r2;
        }
        __syncthreads();
        float inv = 1.0f / fmaxf(sqrtf(red[0]), 1e-12f);
        g_wn[r*DD + t] = val * inv;
    } else if (bx < 416) {
        int gid = (bx - 32)*256 + t;
        int w = gid & 3, lane = (gid >> 2) & 31, tile = gid >> 7;
        int kt = tile % 48, dt = tile / 48;
        int d = dt*16 + (lane >> 2) + (w & 1)*8;
        int c = kt*16 + (lane & 3)*2 + (w >> 1)*8;
        g_wf[gid] = pack2h(W[(size_t)d*CC + c], W[(size_t)d*CC + c + 1]);
    } else if (bx < 544) {
        ((float4*)vt)[(bx - 416)*256 + t] = make_float4(0.f,0.f,0.f,0.f);
    } else {
        ((float4*)g_nrm)[(bx - 544)*256 + t] = make_float4(0.f,0.f,0.f,0.f);
    }
}

// ------------------------------------------------------------------
// k_pre2: block m computes wnW[m,:] = wn[m,:].W  (fp32), wnb[m], and packs
// wnW row into fp16 A-fragment layout g_wsf.
__global__ __launch_bounds__(256) void k_pre2(const float* __restrict__ W,
                                              const float* __restrict__ bias) {
    const int m = blockIdx.x, t = threadIdx.x;
    __shared__ float wns[DD];
    __shared__ float wc[CC];
    __shared__ float red[8];
    wns[t] = g_wn[m*DD + t];
    __syncthreads();
    float s0 = 0.f, s1 = 0.f, s2 = 0.f;
    for (int d = 0; d < DD; ++d) {
        float wd = wns[d];
        const float* Wr = W + (size_t)d*CC;
        s0 += wd * Wr[t];
        s1 += wd * Wr[t + 256];
        s2 += wd * Wr[t + 512];
    }
    wc[t] = s0; wc[t + 256] = s1; wc[t + 512] = s2;
    // wnb
    float bb = wns[t] * bias[t];
    #pragma unroll
    for (int o = 16; o; o >>= 1) bb += __shfl_xor_sync(~0u, bb, o);
    if ((t & 31) == 0) red[t >> 5] = bb;
    __syncthreads();
    if (t == 0) {
        float tot = 0.f;
        #pragma unroll
        for (int i = 0; i < 8; ++i) tot += red[i];
        g_wnb[m] = tot;
    }
    // pack this row's 384 fragment words
    const int r = m & 15, lh = r >> 3, lr = r & 7, dt = m >> 4;
    for (int q = t; q < 384; q += 256) {
        int kt = q >> 3, s = q & 7;
        int lane = 4*lr + (s & 3);
        int wo = lh + (s >> 2)*2;
        int c = kt*16 + (s & 3)*2 + (s >> 2)*8;
        g_wsf[((dt*48 + kt)*32 + lane)*4 + wo] = pack2h(wc[c], wc[c + 1]);
    }
}

// ------------------------------------------------------------------
// k1_mma: grid (32 ntiles, 48): per (b,ntile) 2 GEMM CTAs (dh 0/1) + 1 score CTA.
#define XPITCH 304
#define XBUF   9728                     // one x buffer (32 rows fp16)
#define EP_OFF 19456                    // staging region
#define EPITCH 132
#define SMEM_SZ (EP_OFF + 64*EPITCH*4)  // 53248

__global__ __launch_bounds__(256, 2) void k1_mma(const float* __restrict__ x,
                                                 const float* __restrict__ bias,
                                                 float* __restrict__ xp) {
    extern __shared__ char smc[];
    const uint32_t sb = smem_u32(smc);
    const int by = blockIdx.y;
    const int b = by / 3, typ = by - b*3;
    const int n0 = blockIdx.x * 128;
    const int t = threadIdx.x, w = t >> 5, lane = t & 31;

    const float* xb = x + (size_t)b * CC * HWN + n0;
    const int c0 = t >> 5;
    const int n4 = t & 31;

    float4 vr[4];
    #pragma unroll
    for (int i = 0; i < 4; ++i)
        vr[i] = *(const float4*)(xb + (size_t)(c0 + 8*i)*HWN + n4*4);

    if (typ == 2) {
        // ---------------- score CTA: Z_raw = wnW . x + wnb ----------------
        const int dt = w & 1;
        const int nwb = (w >> 1) * 32;
        float acc[4][4];
        #pragma unroll
        for (int j = 0; j < 4; ++j)
            #pragma unroll
            for (int i = 0; i < 4; ++i) acc[j][i] = 0.f;

        int buf = 0;
        for (int kc = 0; kc < CC; kc += 32, buf ^= 1) {
            {
                char* base = smc + buf*XBUF;
                #pragma unroll
                for (int i = 0; i < 4; ++i) {
                    unsigned p01 = pack2h(vr[i].x, vr[i].y);
                    unsigned p23 = pack2h(vr[i].z, vr[i].w);
                    *(uint2*)(base + (c0 + 8*i)*XPITCH + n4*8) = make_uint2(p01, p23);
                }
            }
            uint4 as[2];
            #pragma unroll
            for (int ks = 0; ks < 2; ++ks)
                as[ks] = *(const uint4*)(g_wsf + ((dt*48 + (kc >> 4) + ks)*32 + lane)*4);
            if (kc + 32 < CC) {
                #pragma unroll
                for (int i = 0; i < 4; ++i)
                    vr[i] = *(const float4*)(xb + (size_t)(kc + 32 + c0 + 8*i)*HWN + n4*4);
            }
            __syncthreads();

            const uint32_t sxb = sb + buf*XBUF;
            #pragma unroll
            for (int ks = 0; ks < 2; ++ks) {
                #pragma unroll
                for (int j = 0; j < 2; ++j) {
                    uint32_t baddr = sxb + (uint32_t)((ks*16 + (lane & 15))*XPITCH
                                   + (nwb + j*16 + ((lane >> 4) << 3))*2);
                    unsigned b0,b1,b2,b3;
                    LDSM_T(b0,b1,b2,b3, baddr);
                    MMA_F16(acc[2*j],   as[ks], b0, b1);
                    MMA_F16(acc[2*j+1], as[ks], b2, b3);
                }
            }
        }
        // stage Z tile [32 m][128 n] and store coalesced
        __syncthreads();
        float* sZ = (float*)(smc + EP_OFF);
        #pragma unroll
        for (int j = 0; j < 4; ++j) {
            int m0 = dt*16 + (lane >> 2);
            int nn = nwb + j*8 + (lane & 3)*2;
            sZ[m0*EPITCH + nn]       = acc[j][0];
            sZ[m0*EPITCH + nn + 1]   = acc[j][1];
            sZ[(m0+8)*EPITCH + nn]     = acc[j][2];
            sZ[(m0+8)*EPITCH + nn + 1] = acc[j][3];
        }
        __syncthreads();
        #pragma unroll
        for (int i = 0; i < 4; ++i) {
            int idx = t + i*256;
            int m = idx >> 5, c4 = idx & 31;
            float4 z = *(float4*)(sZ + m*EPITCH + c4*4);
            float wb = g_wnb[m];
            z.x += wb; z.y += wb; z.z += wb; z.w += wb;
            *(float4*)(g_Z + (size_t)(b*MM + m)*HWN + n0 + c4*4) = z;
        }
        return;
    }

    // ---------------- GEMM CTA (dh half of d) ----------------
    const int dh = typ;
    const int nw = (w >> 2) * 64;

    float acc[2][8][4];
    #pragma unroll
    for (int mt = 0; mt < 2; ++mt)
        #pragma unroll
        for (int nt = 0; nt < 8; ++nt)
            #pragma unroll
            for (int i = 0; i < 4; ++i) acc[mt][nt][i] = 0.f;

    int buf = 0;
    for (int kc = 0; kc < CC; kc += 32, buf ^= 1) {
        {
            char* base = smc + buf*XBUF;
            #pragma unroll
            for (int i = 0; i < 4; ++i) {
                unsigned p01 = pack2h(vr[i].x, vr[i].y);
                unsigned p23 = pack2h(vr[i].z, vr[i].w);
                *(uint2*)(base + (c0 + 8*i)*XPITCH + n4*8) = make_uint2(p01, p23);
            }
        }
        uint4 ah[2][2];
        #pragma unroll
        for (int ks = 0; ks < 2; ++ks)
            #pragma unroll
            for (int mt = 0; mt < 2; ++mt) {
                int dt = dh*8 + (w & 3)*2 + mt;
                int kt = (kc >> 4) + ks;
                ah[ks][mt] = *(const uint4*)(g_wf + ((dt*48 + kt)*32 + lane)*4);
            }
        if (kc + 32 < CC) {
            #pragma unroll
            for (int i = 0; i < 4; ++i)
                vr[i] = *(const float4*)(xb + (size_t)(kc + 32 + c0 + 8*i)*HWN + n4*4);
        }
        __syncthreads();

        const uint32_t sxb = sb + buf*XBUF;
        #pragma unroll
        for (int ks = 0; ks < 2; ++ks) {
            #pragma unroll
            for (int j = 0; j < 4; ++j) {
                uint32_t baddr = sxb + (uint32_t)((ks*16 + (lane & 15))*XPITCH
                               + (nw + j*16 + ((lane >> 4) << 3))*2);
                unsigned b0,b1,b2,b3;
                LDSM_T(b0,b1,b2,b3, baddr);
                #pragma unroll
                for (int mt = 0; mt < 2; ++mt) {
                    MMA_F16(acc[mt][2*j],   ah[ks][mt], b0, b1);
                    MMA_F16(acc[mt][2*j+1], ah[ks][mt], b2, b3);
                }
            }
        }
    }

    const int dbase = (w & 3)*32 + (lane >> 2);
    float bj[2][2];
    #pragma unroll
    for (int mt = 0; mt < 2; ++mt) {
        bj[mt][0] = bias[dh*128 + dbase + mt*16];
        bj[mt][1] = bias[dh*128 + dbase + mt*16 + 8];
    }

    float* s_ep = (float*)(smc + EP_OFF);
    #pragma unroll
    for (int p = 0; p < 2; ++p) {
        __syncthreads();
        if ((w >> 2) == p) {
            #pragma unroll
            for (int mt = 0; mt < 2; ++mt) {
                int d = (w & 3)*32 + mt*16 + (lane >> 2);
                #pragma unroll
                for (int nt = 0; nt < 8; ++nt) {
                    int nl = nt*8 + (lane & 3)*2;
                    s_ep[nl*EPITCH + d]           = acc[mt][nt][0] + bj[mt][0];
                    s_ep[(nl+1)*EPITCH + d]       = acc[mt][nt][1] + bj[mt][0];
                    s_ep[nl*EPITCH + d + 8]       = acc[mt][nt][2] + bj[mt][1];
                    s_ep[(nl+1)*EPITCH + d + 8]   = acc[mt][nt][3] + bj[mt][1];
                }
            }
        }
        __syncthreads();
        #pragma unroll
        for (int i = 0; i < 8; ++i) {
            int idx = t + i*256;
            int row = idx >> 5, c4 = idx & 31;
            float4 v = *(float4*)(s_ep + row*EPITCH + c4*4);
            *(float4*)(xp + (size_t)(b*HWN + n0 + p*64 + row)*DD + dh*128 + c4*4) = v;
        }
        // partial row norms (this CTA's 128 d)
        {
            const int n = t >> 2, q = t & 3;
            const int gn = n0 + p*64 + n;
            float s = 0.f;
            #pragma unroll
            for (int k = 0; k < 8; ++k) {
                float4 xv = *(float4*)(s_ep + n*EPITCH + q*32 + k*4);
                s += xv.x*xv.x + xv.y*xv.y + xv.z*xv.z + xv.w*xv.w;
            }
            s += __shfl_xor_sync(~0u, s, 1, 4);
            s += __shfl_xor_sync(~0u, s, 2, 4);
            if (q == 0) atomicAdd(&g_nrm[b*HWN + gn], s);
        }
    }
}

// ------------------------------------------------------------------
// u[b,m] = NORMC - lse_n(Zs + v) ; Zs = rawZ * inv(nrm) * SCALE
__global__ __launch_bounds__(256) void k2a(int first) {
    int bm = blockIdx.x;
    int b  = bm >> 5;
    const float* z  = g_Z + (size_t)bm * HWN;
    const float* nr = g_nrm + b * HWN;
    const float* vv = g_v + b * HWN;
    int t = threadIdx.x;

    float vals[16];
    float mx = -1e30f;
    #pragma unroll
    for (int i = 0; i < 16; ++i) {
        int idx = t + i*256;
        float zs = z[idx] * inv_from_nrm(nr[idx]) * SCALE;
        vals[i] = first ? zs : zs + vv[idx];
        mx = fmaxf(mx, vals[i]);
    }
    __shared__ float red[8];
    #pragma unroll
    for (int o = 16; o; o >>= 1) mx = fmaxf(mx, __shfl_xor_sync(~0u, mx, o));
    if ((t & 31) == 0) red[t >> 5] = mx;
    __syncthreads();
    if (t < 8) {
        float r = red[t];
        #pragma unroll
        for (int o = 4; o; o >>= 1) r = fmaxf(r, __shfl_xor_sync(0xff, r, o, 8));
        if (t == 0) red[0] = r;
    }
    __syncthreads();
    mx = red[0];
    __syncthreads();

    float s = 0.f;
    #pragma unroll
    for (int i = 0; i < 16; ++i) s += expf(vals[i] - mx);
    #pragma unroll
    for (int o = 16; o; o >>= 1) s += __shfl_xor_sync(~0u, s, o);
    if ((t & 31) == 0) red[t >> 5] = s;
    __syncthreads();
    if (t == 0) {
        float tot = 0.f;
        #pragma unroll
        for (int i = 0; i < 8; ++i) tot += red[i];
        g_u[bm] = NORMC - (mx + logf(tot));
    }
}

// v[b,n] = NORMC - lse_m(Zs + u)
__global__ __launch_bounds__(256) void k2b() {
    int gid = blockIdx.x*256 + threadIdx.x;
    int b = gid >> 12;
    int n = gid & (HWN - 1);
    __shared__ float us[MM];
    if (threadIdx.x < MM) us[threadIdx.x] = g_u[b*MM + threadIdx.x];
    __syncthreads();
    float scal = inv_from_nrm(g_nrm[gid]) * SCALE;
    float vals[MM];
    float mx = -1e30f;
    #pragma unroll
    for (int m = 0; m < MM; ++m) {
        vals[m] = g_Z[(size_t)(b*MM + m)*HWN + n] * scal + us[m];
        mx = fmaxf(mx, vals[m]);
    }
    float s = 0.f;
    #pragma unroll
    for (int m = 0; m < MM; ++m) s += expf(vals[m] - mx);
    g_v[gid] = NORMC - (mx + logf(s));
}

// ------------------------------------------------------------------
// k3: final v inline (column softmax) + aggregation into v_tilde
__global__ __launch_bounds__(256) void k3(const float* __restrict__ xp,
                                          float* __restrict__ vt) {
    int b  = blockIdx.y;
    int n0 = blockIdx.x * 256;
    int t  = threadIdx.x;
    __shared__ float sw[256*36];
    __shared__ float us[MM];
    __shared__ float sinv[256];
    if (t < MM) us[t] = g_u[b*MM + t];
    float myinv = inv_from_nrm(g_nrm[b*HWN + n0 + t]);
    sinv[t] = myinv;
    __syncthreads();

    {
        int n = n0 + t;
        float scal = myinv * SCALE;
        float vals[MM];
        float mx = -1e30f;
        #pragma unroll
        for (int m = 0; m < MM; ++m) {
            vals[m] = g_Z[(size_t)(b*MM + m)*HWN + n] * scal + us[m];
            mx = fmaxf(mx, vals[m]);
        }
        float s = 0.f;
        #pragma unroll
        for (int m = 0; m < MM; ++m) {
            vals[m] = expf(vals[m] - mx);
            s += vals[m];
        }
        float is = 1.0f / s;
        #pragma unroll
        for (int m = 0; m < MM; ++m) sw[t*36 + m] = vals[m] * is;
    }
    __syncthreads();

    float acc[MM];
    #pragma unroll
    for (int m = 0; m < MM; ++m) acc[m] = 0.f;

    for (int nn = 0; nn < 256; ++nn) {
        float xv = xp[(size_t)(b*HWN + n0 + nn)*DD + t] * sinv[nn];
        #pragma unroll
        for (int m4 = 0; m4 < 8; ++m4) {
            float4 w4 = *(float4*)(sw + nn*36 + m4*4);
            acc[m4*4+0] += xv * w4.x;
            acc[m4*4+1] += xv * w4.y;
            acc[m4*4+2] += xv * w4.z;
            acc[m4*4+3] += xv * w4.w;
        }
    }
    #pragma unroll
    for (int m = 0; m < MM; ++m)
        atomicAdd(&vt[(size_t)(b*MM + m)*DD + t], acc[m]);
}

// ------------------------------------------------------------------
extern "C" void kernel_launch(void* const* d_in, const int* in_sizes, int n_in,
                              void* d_out, int out_size) {
    (void)in_sizes; (void)n_in; (void)out_size;
    const float* x    = (const float*)d_in[0];   // [16,768,64,64]
    const float* W    = (const float*)d_in[1];   // [256,768]
    const float* bias = (const float*)d_in[2];   // [256]
    const float* v    = (const float*)d_in[3];   // [32,256]

    float* out = (float*)d_out;
    float* vt  = out;                 // v_tilde [16,32,256]
    float* xp  = out + VT_ELEMS;      // x_proj  [16,4096,256]

    cudaFuncSetAttribute(k1_mma, cudaFuncAttributeMaxDynamicSharedMemorySize, SMEM_SZ);

    k_pre1<<<608, 256>>>(v, W, vt);
    k_pre2<<<32, 256>>>(W, bias);
    k1_mma<<<dim3(32, 48), 256, SMEM_SZ>>>(x, bias, xp);
    k2a<<<512, 256>>>(1);     // u1 (v0 = 0)
    k2b<<<256, 256>>>();      // v1
    k2a<<<512, 256>>>(0);     // u2
    k2b<<<256, 256>>>();      // v2
    k2a<<<512, 256>>>(0);     // u3
    k3<<<dim3(16, 16), 256>>>(xp, vt);   // v3 inline + aggregation
}

// round 13
// speedup vs baseline: 1.9150x; 1.0059x over previous
#include <cuda_runtime.h>
#include <cuda_fp16.h>
#include <cstdint>
#include <math.h>

#define BB 16
#define CC 768
#define HWN 4096
#define DD 256
#define MM 32
#define SCALE 20.0f            // 1/EPS
#define NORMC (-8.32554830f)   // -log(32+4096)
#define EXPNORMC 2.4224806e-4f // e^NORMC = 1/4128
#define INVEXPN  4128.0f       // e^-NORMC
#define VT_ELEMS (BB*MM*DD)

// ---- scratch (device globals; no allocations allowed) ----
__device__ float g_Z[BB*MM*HWN];     // 8 MB: RAW scores xp.wn [b,m,n]
__device__ float g_nrm[BB*HWN];      // per-row sum of squares of x_proj
__device__ float g_su[3*BB*MM];      // S1,S2,S3 row sums (u_k = NORMC - log S_k)
__device__ float g_wn[MM*DD];
__device__ float g_wnb[MM];          // wn . bias
// W as fp16 per-lane mma A-fragments: [dtile 16][ktile 48][lane 32][4 words]
__device__ __align__(16) unsigned g_wf[98304];
// wn.W as fp16 A-fragments: [dtile 2][ktile 48][lane 32][4 words]
__device__ __align__(16) unsigned g_wsf[12288];

__device__ __forceinline__ uint32_t smem_u32(const void* p) {
    uint32_t a;
    asm("{ .reg .u64 t; cvta.to.shared.u64 t, %1; cvt.u32.u64 %0, t; }" : "=r"(a) : "l"(p));
    return a;
}
__device__ __forceinline__ unsigned pack2h(float a, float b) {
    __half ha = __float2half_rn(a), hb = __float2half_rn(b);
    return (unsigned)__half_as_ushort(ha) | ((unsigned)__half_as_ushort(hb) << 16);
}
__device__ __forceinline__ float inv_from_nrm(float nv) {
    return rsqrtf(fmaxf(nv, 1e-24f));
}

#define LDSM_T(r0,r1,r2,r3,addr) \
    asm volatile("ldmatrix.sync.aligned.m8n8.x4.trans.shared.b16 {%0,%1,%2,%3}, [%4];" \
        : "=r"(r0), "=r"(r1), "=r"(r2), "=r"(r3) : "r"(addr))

#define MMA_F16(acc, a, b0v, b1v) \
    asm volatile("mma.sync.aligned.m16n8k16.row.col.f32.f16.f16.f32 " \
        "{%0,%1,%2,%3}, {%4,%5,%6,%7}, {%8,%9}, {%0,%1,%2,%3};" \
        : "+f"((acc)[0]), "+f"((acc)[1]), "+f"((acc)[2]), "+f"((acc)[3]) \
        : "r"((a).x), "r"((a).y), "r"((a).z), "r"((a).w), "r"(b0v), "r"(b1v))

// ------------------------------------------------------------------
// k_pre1: [0,32) wnorm (+zero g_su) ; [32,416) wsplit ; [416,544) zero vt ;
//         [544,608) zero g_nrm
__global__ __launch_bounds__(256) void k_pre1(const float* __restrict__ v,
                                              const float* __restrict__ W,
                                              float* __restrict__ vt) {
    const int bx = blockIdx.x, t = threadIdx.x;
    if (bx < 32) {
        int zi = bx*256 + t;
        if (zi < 3*BB*MM) g_su[zi] = 0.0f;
        int r = bx;
        float val = v[r*DD + t];
        float s = val * val;
        #pragma unroll
        for (int o = 16; o; o >>= 1) s += __shfl_xor_sync(~0u, s, o);
        __shared__ float red[8];
        if ((t & 31) == 0) red[t >> 5] = s;
        __syncthreads();
        if (t < 8) {
            float r2 = red[t];
            #pragma unroll
            for (int o = 4; o; o >>= 1) r2 += __shfl_xor_sync(0xff, r2, o, 8);
            if (t == 0) red[0] = r2;
        }
        __syncthreads();
        float inv = 1.0f / fmaxf(sqrtf(red[0]), 1e-12f);
        g_wn[r*DD + t] = val * inv;
    } else if (bx < 416) {
        int gid = (bx - 32)*256 + t;
        int w = gid & 3, lane = (gid >> 2) & 31, tile = gid >> 7;
        int kt = tile % 48, dt = tile / 48;
        int d = dt*16 + (lane >> 2) + (w & 1)*8;
        int c = kt*16 + (lane & 3)*2 + (w >> 1)*8;
        g_wf[gid] = pack2h(W[(size_t)d*CC + c], W[(size_t)d*CC + c + 1]);
    } else if (bx < 544) {
        ((float4*)vt)[(bx - 416)*256 + t] = make_float4(0.f,0.f,0.f,0.f);
    } else {
        ((float4*)g_nrm)[(bx - 544)*256 + t] = make_float4(0.f,0.f,0.f,0.f);
    }
}

// ------------------------------------------------------------------
// k_pre2: block m computes wnW[m,:] = wn[m,:].W, wnb[m], packs A-fragments.
__global__ __launch_bounds__(256) void k_pre2(const float* __restrict__ W,
                                              const float* __restrict__ bias) {
    const int m = blockIdx.x, t = threadIdx.x;
    __shared__ float wns[DD];
    __shared__ float wc[CC];
    __shared__ float red[8];
    wns[t] = g_wn[m*DD + t];
    __syncthreads();
    float s0 = 0.f, s1 = 0.f, s2 = 0.f;
    for (int d = 0; d < DD; ++d) {
        float wd = wns[d];
        const float* Wr = W + (size_t)d*CC;
        s0 += wd * Wr[t];
        s1 += wd * Wr[t + 256];
        s2 += wd * Wr[t + 512];
    }
    wc[t] = s0; wc[t + 256] = s1; wc[t + 512] = s2;
    float bb = wns[t] * bias[t];
    #pragma unroll
    for (int o = 16; o; o >>= 1) bb += __shfl_xor_sync(~0u, bb, o);
    if ((t & 31) == 0) red[t >> 5] = bb;
    __syncthreads();
    if (t == 0) {
        float tot = 0.f;
        #pragma unroll
        for (int i = 0; i < 8; ++i) tot += red[i];
        g_wnb[m] = tot;
    }
    const int r = m & 15, lh = r >> 3, lr = r & 7, dt = m >> 4;
    for (int q = t; q < 384; q += 256) {
        int kt = q >> 3, s = q & 7;
        int lane = 4*lr + (s & 3);
        int wo = lh + (s >> 2)*2;
        int c = kt*16 + (s & 3)*2 + (s >> 2)*8;
        g_wsf[((dt*48 + kt)*32 + lane)*4 + wo] = pack2h(wc[c], wc[c + 1]);
    }
}

// ------------------------------------------------------------------
// k1_mma: grid (32 ntiles, 48): per (b,ntile) 2 GEMM CTAs (dh 0/1) + 1 score CTA.
#define XPITCH 304
#define XBUF   9728
#define EP_OFF 19456
#define EPITCH 132
#define SMEM_SZ (EP_OFF + 64*EPITCH*4)  // 53248

__global__ __launch_bounds__(256, 2) void k1_mma(const float* __restrict__ x,
                                                 const float* __restrict__ bias,
                                                 float* __restrict__ xp) {
    extern __shared__ char smc[];
    const uint32_t sb = smem_u32(smc);
    const int by = blockIdx.y;
    const int b = by / 3, typ = by - b*3;
    const int n0 = blockIdx.x * 128;
    const int t = threadIdx.x, w = t >> 5, lane = t & 31;

    const float* xb = x + (size_t)b * CC * HWN + n0;
    const int c0 = t >> 5;
    const int n4 = t & 31;

    float4 vr[4];
    #pragma unroll
    for (int i = 0; i < 4; ++i)
        vr[i] = *(const float4*)(xb + (size_t)(c0 + 8*i)*HWN + n4*4);

    if (typ == 2) {
        // ---------------- score CTA: Z_raw = wnW . x + wnb ----------------
        const int dt = w & 1;
        const int nwb = (w >> 1) * 32;
        float acc[4][4];
        #pragma unroll
        for (int j = 0; j < 4; ++j)
            #pragma unroll
            for (int i = 0; i < 4; ++i) acc[j][i] = 0.f;

        int buf = 0;
        for (int kc = 0; kc < CC; kc += 32, buf ^= 1) {
            {
                char* base = smc + buf*XBUF;
                #pragma unroll
                for (int i = 0; i < 4; ++i) {
                    unsigned p01 = pack2h(vr[i].x, vr[i].y);
                    unsigned p23 = pack2h(vr[i].z, vr[i].w);
                    *(uint2*)(base + (c0 + 8*i)*XPITCH + n4*8) = make_uint2(p01, p23);
                }
            }
            uint4 as[2];
            #pragma unroll
            for (int ks = 0; ks < 2; ++ks)
                as[ks] = *(const uint4*)(g_wsf + ((dt*48 + (kc >> 4) + ks)*32 + lane)*4);
            if (kc + 32 < CC) {
                #pragma unroll
                for (int i = 0; i < 4; ++i)
                    vr[i] = *(const float4*)(xb + (size_t)(kc + 32 + c0 + 8*i)*HWN + n4*4);
            }
            __syncthreads();

            const uint32_t sxb = sb + buf*XBUF;
            #pragma unroll
            for (int ks = 0; ks < 2; ++ks) {
                #pragma unroll
                for (int j = 0; j < 2; ++j) {
                    uint32_t baddr = sxb + (uint32_t)((ks*16 + (lane & 15))*XPITCH
                                   + (nwb + j*16 + ((lane >> 4) << 3))*2);
                    unsigned b0,b1,b2,b3;
                    LDSM_T(b0,b1,b2,b3, baddr);
                    MMA_F16(acc[2*j],   as[ks], b0, b1);
                    MMA_F16(acc[2*j+1], as[ks], b2, b3);
                }
            }
        }
        __syncthreads();
        float* sZ = (float*)(smc + EP_OFF);
        #pragma unroll
        for (int j = 0; j < 4; ++j) {
            int m0 = dt*16 + (lane >> 2);
            int nn = nwb + j*8 + (lane & 3)*2;
            sZ[m0*EPITCH + nn]       = acc[j][0];
            sZ[m0*EPITCH + nn + 1]   = acc[j][1];
            sZ[(m0+8)*EPITCH + nn]     = acc[j][2];
            sZ[(m0+8)*EPITCH + nn + 1] = acc[j][3];
        }
        __syncthreads();
        #pragma unroll
        for (int i = 0; i < 4; ++i) {
            int idx = t + i*256;
            int m = idx >> 5, c4 = idx & 31;
            float4 z = *(float4*)(sZ + m*EPITCH + c4*4);
            float wb = g_wnb[m];
            z.x += wb; z.y += wb; z.z += wb; z.w += wb;
            *(float4*)(g_Z + (size_t)(b*MM + m)*HWN + n0 + c4*4) = z;
        }
        return;
    }

    // ---------------- GEMM CTA (dh half of d) ----------------
    const int dh = typ;
    const int nw = (w >> 2) * 64;

    float acc[2][8][4];
    #pragma unroll
    for (int mt = 0; mt < 2; ++mt)
        #pragma unroll
        for (int nt = 0; nt < 8; ++nt)
            #pragma unroll
            for (int i = 0; i < 4; ++i) acc[mt][nt][i] = 0.f;

    int buf = 0;
    for (int kc = 0; kc < CC; kc += 32, buf ^= 1) {
        {
            char* base = smc + buf*XBUF;
            #pragma unroll
            for (int i = 0; i < 4; ++i) {
                unsigned p01 = pack2h(vr[i].x, vr[i].y);
                unsigned p23 = pack2h(vr[i].z, vr[i].w);
                *(uint2*)(base + (c0 + 8*i)*XPITCH + n4*8) = make_uint2(p01, p23);
            }
        }
        uint4 ah[2][2];
        #pragma unroll
        for (int ks = 0; ks < 2; ++ks)
            #pragma unroll
            for (int mt = 0; mt < 2; ++mt) {
                int dt = dh*8 + (w & 3)*2 + mt;
                int kt = (kc >> 4) + ks;
                ah[ks][mt] = *(const uint4*)(g_wf + ((dt*48 + kt)*32 + lane)*4);
            }
        if (kc + 32 < CC) {
            #pragma unroll
            for (int i = 0; i < 4; ++i)
                vr[i] = *(const float4*)(xb + (size_t)(kc + 32 + c0 + 8*i)*HWN + n4*4);
        }
        __syncthreads();

        const uint32_t sxb = sb + buf*XBUF;
        #pragma unroll
        for (int ks = 0; ks < 2; ++ks) {
            #pragma unroll
            for (int j = 0; j < 4; ++j) {
                uint32_t baddr = sxb + (uint32_t)((ks*16 + (lane & 15))*XPITCH
                               + (nw + j*16 + ((lane >> 4) << 3))*2);
                unsigned b0,b1,b2,b3;
                LDSM_T(b0,b1,b2,b3, baddr);
                #pragma unroll
                for (int mt = 0; mt < 2; ++mt) {
                    MMA_F16(acc[mt][2*j],   ah[ks][mt], b0, b1);
                    MMA_F16(acc[mt][2*j+1], ah[ks][mt], b2, b3);
                }
            }
        }
    }

    const int dbase = (w & 3)*32 + (lane >> 2);
    float bj[2][2];
    #pragma unroll
    for (int mt = 0; mt < 2; ++mt) {
        bj[mt][0] = bias[dh*128 + dbase + mt*16];
        bj[mt][1] = bias[dh*128 + dbase + mt*16 + 8];
    }

    float* s_ep = (float*)(smc + EP_OFF);
    #pragma unroll
    for (int p = 0; p < 2; ++p) {
        __syncthreads();
        if ((w >> 2) == p) {
            #pragma unroll
            for (int mt = 0; mt < 2; ++mt) {
                int d = (w & 3)*32 + mt*16 + (lane >> 2);
                #pragma unroll
                for (int nt = 0; nt < 8; ++nt) {
                    int nl = nt*8 + (lane & 3)*2;
                    s_ep[nl*EPITCH + d]           = acc[mt][nt][0] + bj[mt][0];
                    s_ep[(nl+1)*EPITCH + d]       = acc[mt][nt][1] + bj[mt][0];
                    s_ep[nl*EPITCH + d + 8]       = acc[mt][nt][2] + bj[mt][1];
                    s_ep[(nl+1)*EPITCH + d + 8]   = acc[mt][nt][3] + bj[mt][1];
                }
            }
        }
        __syncthreads();
        #pragma unroll
        for (int i = 0; i < 8; ++i) {
            int idx = t + i*256;
            int row = idx >> 5, c4 = idx & 31;
            float4 v = *(float4*)(s_ep + row*EPITCH + c4*4);
            *(float4*)(xp + (size_t)(b*HWN + n0 + p*64 + row)*DD + dh*128 + c4*4) = v;
        }
        {
            const int n = t >> 2, q = t & 3;
            const int gn = n0 + p*64 + n;
            float s = 0.f;
            #pragma unroll
            for (int k = 0; k < 8; ++k) {
                float4 xv = *(float4*)(s_ep + n*EPITCH + q*32 + k*4);
                s += xv.x*xv.x + xv.y*xv.y + xv.z*xv.z + xv.w*xv.w;
            }
            s += __shfl_xor_sync(~0u, s, 1, 4);
            s += __shfl_xor_sync(~0u, s, 2, 4);
            if (q == 0) atomicAdd(&g_nrm[b*HWN + gn], s);
        }
    }
}

// ------------------------------------------------------------------
// kF: column pass. Computes (unless first) u[m] = NORMC - log(suIn[m]) and
// v[n] = NORMC - log(sum_m e^{Zs+u}); accumulates suOut[m] += sum_n e^{Zs+v}.
// first=1: u=0, e^v treated as 1 -> suOut[m] = sum_n e^{Zs} (the u1 sums).
__global__ __launch_bounds__(256) void kF(int inOff, int outOff, int first) {
    const int b = blockIdx.x >> 4, ch = blockIdx.x & 15;
    const int t = threadIdx.x;
    const int n = ch*256 + t;
    __shared__ float us[MM], einv[MM];
    __shared__ float ev[256];
    __shared__ float ex[256*33];
    __shared__ float red[MM*9];
    if (t < MM) {
        if (first) { us[t] = 0.f; einv[t] = 1.f; }
        else {
            float S = g_su[inOff + b*MM + t];
            us[t]   = NORMC - logf(S);
            einv[t] = INVEXPN * S;         // e^{-u}
        }
    }
    __syncthreads();
    float scal = inv_from_nrm(g_nrm[b*HWN + n]) * SCALE;
    float s = 0.f;
    #pragma unroll
    for (int m = 0; m < MM; ++m) {
        float e = expf(g_Z[(size_t)(b*MM + m)*HWN + n] * scal + us[m]);
        ex[t*33 + m] = e;
        s += e;
    }
    ev[t] = first ? 1.f : EXPNORMC / s;    // e^{v[n]}
    __syncthreads();
    const int m = t & 31, g = t >> 5;
    float ps = 0.f;
    #pragma unroll
    for (int j = 0; j < 32; ++j)
        ps += ex[(g*32 + j)*33 + m] * ev[g*32 + j];
    red[m*9 + g] = ps;
    __syncthreads();
    if (t < MM) {
        float tot = 0.f;
        #pragma unroll
        for (int g2 = 0; g2 < 8; ++g2) tot += red[t*9 + g2];
        atomicAdd(&g_su[outOff + b*MM + t], tot * einv[t]);
    }
}

// ------------------------------------------------------------------
// k3: u3 from S3 sums, final v inline (column softmax), aggregate v_tilde.
__global__ __launch_bounds__(256) void k3(const float* __restrict__ xp,
                                          float* __restrict__ vt) {
    int b  = blockIdx.y;
    int n0 = blockIdx.x * 256;
    int t  = threadIdx.x;
    __shared__ float sw[256*36];
    __shared__ float us[MM];
    __shared__ float sinv[256];
    if (t < MM) us[t] = NORMC - logf(g_su[2*BB*MM + b*MM + t]);
    float myinv = inv_from_nrm(g_nrm[b*HWN + n0 + t]);
    sinv[t] = myinv;
    __syncthreads();

    {
        int n = n0 + t;
        float scal = myinv * SCALE;
        float vals[MM];
        float s = 0.f;
        #pragma unroll
        for (int m = 0; m < MM; ++m) {
            vals[m] = expf(g_Z[(size_t)(b*MM + m)*HWN + n] * scal + us[m]);
            s += vals[m];
        }
        float is = 1.0f / s;
        #pragma unroll
        for (int m = 0; m < MM; ++m) sw[t*36 + m] = vals[m] * is;
    }
    __syncthreads();

    float acc[MM];
    #pragma unroll
    for (int m = 0; m < MM; ++m) acc[m] = 0.f;

    for (int nn = 0; nn < 256; ++nn) {
        float xv = xp[(size_t)(b*HWN + n0 + nn)*DD + t] * sinv[nn];
        #pragma unroll
        for (int m4 = 0; m4 < 8; ++m4) {
            float4 w4 = *(float4*)(sw + nn*36 + m4*4);
            acc[m4*4+0] += xv * w4.x;
            acc[m4*4+1] += xv * w4.y;
            acc[m4*4+2] += xv * w4.z;
            acc[m4*4+3] += xv * w4.w;
        }
    }
    #pragma unroll
    for (int m = 0; m < MM; ++m)
        atomicAdd(&vt[(size_t)(b*MM + m)*DD + t], acc[m]);
}

// ------------------------------------------------------------------
extern "C" void kernel_launch(void* const* d_in, const int* in_sizes, int n_in,
                              void* d_out, int out_size) {
    (void)in_sizes; (void)n_in; (void)out_size;
    const float* x    = (const float*)d_in[0];   // [16,768,64,64]
    const float* W    = (const float*)d_in[1];   // [256,768]
    const float* bias = (const float*)d_in[2];   // [256]
    const float* v    = (const float*)d_in[3];   // [32,256]

    float* out = (float*)d_out;
    float* vt  = out;                 // v_tilde [16,32,256]
    float* xp  = out + VT_ELEMS;      // x_proj  [16,4096,256]

    cudaFuncSetAttribute(k1_mma, cudaFuncAttributeMaxDynamicSharedMemorySize, SMEM_SZ);

    k_pre1<<<608, 256>>>(v, W, vt);
    k_pre2<<<32, 256>>>(W, bias);
    k1_mma<<<dim3(32, 48), 256, SMEM_SZ>>>(x, bias, xp);
    kF<<<256, 256>>>(0, 0, 1);                 // S1 = sums for u1
    kF<<<256, 256>>>(0, BB*MM, 0);             // u1 -> v1 -> S2
    kF<<<256, 256>>>(BB*MM, 2*BB*MM, 0);       // u2 -> v2 -> S3
    k3<<<dim3(16, 16), 256>>>(xp, vt);         // u3 -> v3 inline + aggregation
}

// round 17
// speedup vs baseline: 1.9209x; 1.0031x over previous
#include <cuda_runtime.h>
#include <cuda_fp16.h>
#include <cstdint>
#include <math.h>

#define BB 16
#define CC 768
#define HWN 4096
#define DD 256
#define MM 32
#define SCALE 20.0f            // 1/EPS
#define NORMC (-8.32554830f)   // -log(32+4096)
#define EXPNORMC 2.4224806e-4f // e^NORMC = 1/4128
#define INVEXPN  4128.0f       // e^-NORMC
#define VT_ELEMS (BB*MM*DD)

// ---- scratch (device globals; no allocations allowed) ----
__device__ float g_Z[BB*MM*HWN];     // 8 MB: RAW scores xp.wn [b,m,n]
__device__ float g_nrm[BB*HWN];      // per-row sum of squares of x_proj
__device__ float g_su[3*BB*MM];      // S1,S2,S3 row sums (u_k = NORMC - log S_k)
__device__ float g_wn[MM*DD];
__device__ float g_wnb[MM];          // wn . bias
// W as fp16 per-lane mma A-fragments: [dtile 16][ktile 48][lane 32][4 words]
__device__ __align__(16) unsigned g_wf[98304];
// wn.W as fp16 A-fragments: [dtile 2][ktile 48][lane 32][4 words]
__device__ __align__(16) unsigned g_wsf[12288];

__device__ __forceinline__ uint32_t smem_u32(const void* p) {
    uint32_t a;
    asm("{ .reg .u64 t; cvta.to.shared.u64 t, %1; cvt.u32.u64 %0, t; }" : "=r"(a) : "l"(p));
    return a;
}
__device__ __forceinline__ unsigned pack2h(float a, float b) {
    __half ha = __float2half_rn(a), hb = __float2half_rn(b);
    return (unsigned)__half_as_ushort(ha) | ((unsigned)__half_as_ushort(hb) << 16);
}
__device__ __forceinline__ float inv_from_nrm(float nv) {
    return rsqrtf(fmaxf(nv, 1e-24f));
}

#define LDSM_T(r0,r1,r2,r3,addr) \
    asm volatile("ldmatrix.sync.aligned.m8n8.x4.trans.shared.b16 {%0,%1,%2,%3}, [%4];" \
        : "=r"(r0), "=r"(r1), "=r"(r2), "=r"(r3) : "r"(addr))

#define MMA_F16(acc, a, b0v, b1v) \
    asm volatile("mma.sync.aligned.m16n8k16.row.col.f32.f16.f16.f32 " \
        "{%0,%1,%2,%3}, {%4,%5,%6,%7}, {%8,%9}, {%0,%1,%2,%3};" \
        : "+f"((acc)[0]), "+f"((acc)[1]), "+f"((acc)[2]), "+f"((acc)[3]) \
        : "r"((a).x), "r"((a).y), "r"((a).z), "r"((a).w), "r"(b0v), "r"(b1v))

// ------------------------------------------------------------------
// k_pre1: [0,32) wnorm (+zero g_su) ; [32,416) wsplit ; [416,544) zero vt ;
//         [544,608) zero g_nrm
__global__ __launch_bounds__(256) void k_pre1(const float* __restrict__ v,
                                              const float* __restrict__ W,
                                              float* __restrict__ vt) {
    const int bx = blockIdx.x, t = threadIdx.x;
    if (bx < 32) {
        int zi = bx*256 + t;
        if (zi < 3*BB*MM) g_su[zi] = 0.0f;
        int r = bx;
        float val = v[r*DD + t];
        float s = val * val;
        #pragma unroll
        for (int o = 16; o; o >>= 1) s += __shfl_xor_sync(~0u, s, o);
        __shared__ float red[8];
        if ((t & 31) == 0) red[t >> 5] = s;
        __syncthreads();
        if (t < 8) {
            float r2 = red[t];
            #pragma unroll
            for (int o = 4; o; o >>= 1) r2 += __shfl_xor_sync(0xff, r2, o, 8);
            if (t == 0) red[0] = r2;
        }
        __syncthreads();
        float inv = 1.0f / fmaxf(sqrtf(red[0]), 1e-12f);
        g_wn[r*DD + t] = val * inv;
    } else if (bx < 416) {
        int gid = (bx - 32)*256 + t;
        int w = gid & 3, lane = (gid >> 2) & 31, tile = gid >> 7;
        int kt = tile % 48, dt = tile / 48;
        int d = dt*16 + (lane >> 2) + (w & 1)*8;
        int c = kt*16 + (lane & 3)*2 + (w >> 1)*8;
        g_wf[gid] = pack2h(W[(size_t)d*CC + c], W[(size_t)d*CC + c + 1]);
    } else if (bx < 544) {
        ((float4*)vt)[(bx - 416)*256 + t] = make_float4(0.f,0.f,0.f,0.f);
    } else {
        ((float4*)g_nrm)[(bx - 544)*256 + t] = make_float4(0.f,0.f,0.f,0.f);
    }
}

// ------------------------------------------------------------------
// k_pre2: block m computes wnW[m,:] = wn[m,:].W, wnb[m], packs A-fragments.
__global__ __launch_bounds__(256) void k_pre2(const float* __restrict__ W,
                                              const float* __restrict__ bias) {
    const int m = blockIdx.x, t = threadIdx.x;
    __shared__ float wns[DD];
    __shared__ float wc[CC];
    __shared__ float red[8];
    wns[t] = g_wn[m*DD + t];
    __syncthreads();
    float s0 = 0.f, s1 = 0.f, s2 = 0.f;
    for (int d = 0; d < DD; ++d) {
        float wd = wns[d];
        const float* Wr = W + (size_t)d*CC;
        s0 += wd * Wr[t];
        s1 += wd * Wr[t + 256];
        s2 += wd * Wr[t + 512];
    }
    wc[t] = s0; wc[t + 256] = s1; wc[t + 512] = s2;
    float bb = wns[t] * bias[t];
    #pragma unroll
    for (int o = 16; o; o >>= 1) bb += __shfl_xor_sync(~0u, bb, o);
    if ((t & 31) == 0) red[t >> 5] = bb;
    __syncthreads();
    if (t == 0) {
        float tot = 0.f;
        #pragma unroll
        for (int i = 0; i < 8; ++i) tot += red[i];
        g_wnb[m] = tot;
    }
    const int r = m & 15, lh = r >> 3, lr = r & 7, dt = m >> 4;
    for (int q = t; q < 384; q += 256) {
        int kt = q >> 3, s = q & 7;
        int lane = 4*lr + (s & 3);
        int wo = lh + (s >> 2)*2;
        int c = kt*16 + (s & 3)*2 + (s >> 2)*8;
        g_wsf[((dt*48 + kt)*32 + lane)*4 + wo] = pack2h(wc[c], wc[c + 1]);
    }
}

// ------------------------------------------------------------------
// k1_mma: grid (32 ntiles, 48): per (b,ntile) 2 GEMM CTAs (dh 0/1) + 1 score CTA.
#define XPITCH 304
#define XBUF   9728
#define EP_OFF 19456
#define EPITCH 132
#define SMEM_SZ (EP_OFF + 64*EPITCH*4)  // 53248

__global__ __launch_bounds__(256, 2) void k1_mma(const float* __restrict__ x,
                                                 const float* __restrict__ bias,
                                                 float* __restrict__ xp) {
    extern __shared__ char smc[];
    const uint32_t sb = smem_u32(smc);
    const int by = blockIdx.y;
    const int b = by / 3, typ = by - b*3;
    const int n0 = blockIdx.x * 128;
    const int t = threadIdx.x, w = t >> 5, lane = t & 31;

    const float* xb = x + (size_t)b * CC * HWN + n0;
    const int c0 = t >> 5;
    const int n4 = t & 31;

    float4 vr[4];
    #pragma unroll
    for (int i = 0; i < 4; ++i)
        vr[i] = *(const float4*)(xb + (size_t)(c0 + 8*i)*HWN + n4*4);

    if (typ == 2) {
        // ---------------- score CTA: Z_raw = wnW . x + wnb ----------------
        const int dt = w & 1;
        const int nwb = (w >> 1) * 32;
        float acc[4][4];
        #pragma unroll
        for (int j = 0; j < 4; ++j)
            #pragma unroll
            for (int i = 0; i < 4; ++i) acc[j][i] = 0.f;

        int buf = 0;
        for (int kc = 0; kc < CC; kc += 32, buf ^= 1) {
            {
                char* base = smc + buf*XBUF;
                #pragma unroll
                for (int i = 0; i < 4; ++i) {
                    unsigned p01 = pack2h(vr[i].x, vr[i].y);
                    unsigned p23 = pack2h(vr[i].z, vr[i].w);
                    *(uint2*)(base + (c0 + 8*i)*XPITCH + n4*8) = make_uint2(p01, p23);
                }
            }
            uint4 as[2];
            #pragma unroll
            for (int ks = 0; ks < 2; ++ks)
                as[ks] = *(const uint4*)(g_wsf + ((dt*48 + (kc >> 4) + ks)*32 + lane)*4);
            if (kc + 32 < CC) {
                #pragma unroll
                for (int i = 0; i < 4; ++i)
                    vr[i] = *(const float4*)(xb + (size_t)(kc + 32 + c0 + 8*i)*HWN + n4*4);
            }
            __syncthreads();

            const uint32_t sxb = sb + buf*XBUF;
            #pragma unroll
            for (int ks = 0; ks < 2; ++ks) {
                #pragma unroll
                for (int j = 0; j < 2; ++j) {
                    uint32_t baddr = sxb + (uint32_t)((ks*16 + (lane & 15))*XPITCH
                                   + (nwb + j*16 + ((lane >> 4) << 3))*2);
                    unsigned b0,b1,b2,b3;
                    LDSM_T(b0,b1,b2,b3, baddr);
                    MMA_F16(acc[2*j],   as[ks], b0, b1);
                    MMA_F16(acc[2*j+1], as[ks], b2, b3);
                }
            }
        }
        __syncthreads();
        float* sZ = (float*)(smc + EP_OFF);
        #pragma unroll
        for (int j = 0; j < 4; ++j) {
            int m0 = dt*16 + (lane >> 2);
            int nn = nwb + j*8 + (lane & 3)*2;
            sZ[m0*EPITCH + nn]       = acc[j][0];
            sZ[m0*EPITCH + nn + 1]   = acc[j][1];
            sZ[(m0+8)*EPITCH + nn]     = acc[j][2];
            sZ[(m0+8)*EPITCH + nn + 1] = acc[j][3];
        }
        __syncthreads();
        #pragma unroll
        for (int i = 0; i < 4; ++i) {
            int idx = t + i*256;
            int m = idx >> 5, c4 = idx & 31;
            float4 z = *(float4*)(sZ + m*EPITCH + c4*4);
            float wb = g_wnb[m];
            z.x += wb; z.y += wb; z.z += wb; z.w += wb;
            *(float4*)(g_Z + (size_t)(b*MM + m)*HWN + n0 + c4*4) = z;
        }
        return;
    }

    // ---------------- GEMM CTA (dh half of d) ----------------
    const int dh = typ;
    const int nw = (w >> 2) * 64;

    float acc[2][8][4];
    #pragma unroll
    for (int mt = 0; mt < 2; ++mt)
        #pragma unroll
        for (int nt = 0; nt < 8; ++nt)
            #pragma unroll
            for (int i = 0; i < 4; ++i) acc[mt][nt][i] = 0.f;

    int buf = 0;
    for (int kc = 0; kc < CC; kc += 32, buf ^= 1) {
        {
            char* base = smc + buf*XBUF;
            #pragma unroll
            for (int i = 0; i < 4; ++i) {
                unsigned p01 = pack2h(vr[i].x, vr[i].y);
                unsigned p23 = pack2h(vr[i].z, vr[i].w);
                *(uint2*)(base + (c0 + 8*i)*XPITCH + n4*8) = make_uint2(p01, p23);
            }
        }
        uint4 ah[2][2];
        #pragma unroll
        for (int ks = 0; ks < 2; ++ks)
            #pragma unroll
            for (int mt = 0; mt < 2; ++mt) {
                int dt = dh*8 + (w & 3)*2 + mt;
                int kt = (kc >> 4) + ks;
                ah[ks][mt] = *(const uint4*)(g_wf + ((dt*48 + kt)*32 + lane)*4);
            }
        if (kc + 32 < CC) {
            #pragma unroll
            for (int i = 0; i < 4; ++i)
                vr[i] = *(const float4*)(xb + (size_t)(kc + 32 + c0 + 8*i)*HWN + n4*4);
        }
        __syncthreads();

        const uint32_t sxb = sb + buf*XBUF;
        #pragma unroll
        for (int ks = 0; ks < 2; ++ks) {
            #pragma unroll
            for (int j = 0; j < 4; ++j) {
                uint32_t baddr = sxb + (uint32_t)((ks*16 + (lane & 15))*XPITCH
                               + (nw + j*16 + ((lane >> 4) << 3))*2);
                unsigned b0,b1,b2,b3;
                LDSM_T(b0,b1,b2,b3, baddr);
                #pragma unroll
                for (int mt = 0; mt < 2; ++mt) {
                    MMA_F16(acc[mt][2*j],   ah[ks][mt], b0, b1);
                    MMA_F16(acc[mt][2*j+1], ah[ks][mt], b2, b3);
                }
            }
        }
    }

    const int dbase = (w & 3)*32 + (lane >> 2);
    float bj[2][2];
    #pragma unroll
    for (int mt = 0; mt < 2; ++mt) {
        bj[mt][0] = bias[dh*128 + dbase + mt*16];
        bj[mt][1] = bias[dh*128 + dbase + mt*16 + 8];
    }

    float* s_ep = (float*)(smc + EP_OFF);
    #pragma unroll
    for (int p = 0; p < 2; ++p) {
        __syncthreads();
        if ((w >> 2) == p) {
            #pragma unroll
            for (int mt = 0; mt < 2; ++mt) {
                int d = (w & 3)*32 + mt*16 + (lane >> 2);
                #pragma unroll
                for (int nt = 0; nt < 8; ++nt) {
                    int nl = nt*8 + (lane & 3)*2;
                    s_ep[nl*EPITCH + d]           = acc[mt][nt][0] + bj[mt][0];
                    s_ep[(nl+1)*EPITCH + d]       = acc[mt][nt][1] + bj[mt][0];
                    s_ep[nl*EPITCH + d + 8]       = acc[mt][nt][2] + bj[mt][1];
                    s_ep[(nl+1)*EPITCH + d + 8]   = acc[mt][nt][3] + bj[mt][1];
                }
            }
        }
        __syncthreads();
        #pragma unroll
        for (int i = 0; i < 8; ++i) {
            int idx = t + i*256;
            int row = idx >> 5, c4 = idx & 31;
            float4 v = *(float4*)(s_ep + row*EPITCH + c4*4);
            *(float4*)(xp + (size_t)(b*HWN + n0 + p*64 + row)*DD + dh*128 + c4*4) = v;
        }
        {
            const int n = t >> 2, q = t & 3;
            const int gn = n0 + p*64 + n;
            float s = 0.f;
            #pragma unroll
            for (int k = 0; k < 8; ++k) {
                float4 xv = *(float4*)(s_ep + n*EPITCH + q*32 + k*4);
                s += xv.x*xv.x + xv.y*xv.y + xv.z*xv.z + xv.w*xv.w;
            }
            s += __shfl_xor_sync(~0u, s, 1, 4);
            s += __shfl_xor_sync(~0u, s, 2, 4);
            if (q == 0) atomicAdd(&g_nrm[b*HWN + gn], s);
        }
    }
}

// ------------------------------------------------------------------
// kF: column pass carrying row-sums forward. 128 columns per block,
// 128 threads, grid = 16 b x 32 chunks = 512 blocks (load balance).
__global__ __launch_bounds__(128) void kF(int inOff, int outOff, int first) {
    const int b = blockIdx.x >> 5, ch = blockIdx.x & 31;
    const int t = threadIdx.x;
    const int n = ch*128 + t;
    __shared__ float us[MM], einv[MM];
    __shared__ float ev[128];
    __shared__ float ex[128*33];
    __shared__ float red[MM*5];
    if (t < MM) {
        if (first) { us[t] = 0.f; einv[t] = 1.f; }
        else {
            float S = g_su[inOff + b*MM + t];
            us[t]   = NORMC - logf(S);
            einv[t] = INVEXPN * S;
        }
    }
    __syncthreads();
    float scal = inv_from_nrm(g_nrm[b*HWN + n]) * SCALE;
    float s = 0.f;
    #pragma unroll
    for (int m = 0; m < MM; ++m) {
        float e = expf(g_Z[(size_t)(b*MM + m)*HWN + n] * scal + us[m]);
        ex[t*33 + m] = e;
        s += e;
    }
    ev[t] = first ? 1.f : EXPNORMC / s;
    __syncthreads();
    const int m = t & 31, g = t >> 5;          // 4 groups of 32 columns
    float ps = 0.f;
    #pragma unroll
    for (int j = 0; j < 32; ++j)
        ps += ex[(g*32 + j)*33 + m] * ev[g*32 + j];
    red[m*5 + g] = ps;
    __syncthreads();
    if (t < MM) {
        float tot = 0.f;
        #pragma unroll
        for (int g2 = 0; g2 < 4; ++g2) tot += red[t*5 + g2];
        atomicAdd(&g_su[outOff + b*MM + t], tot * einv[t]);
    }
}

// ------------------------------------------------------------------
// k3: u3 from S3 sums, final v inline (column softmax), SIMT aggregation.
// Grid (16 n-chunks, 32 = b*2+dh) = 512 CTAs for load balance.
// Softmax: thread = column (256). Aggregation: d = dh*128 + (t&127),
// n-half = t>>7 (each thread covers 128 n).
__global__ __launch_bounds__(256) void k3(const float* __restrict__ xp,
                                          float* __restrict__ vt) {
    int b  = blockIdx.y >> 1, dh = blockIdx.y & 1;
    int n0 = blockIdx.x * 256;
    int t  = threadIdx.x;
    __shared__ float sw[256*36];
    __shared__ float us[MM];
    __shared__ float sinv[256];
    if (t < MM) us[t] = NORMC - logf(g_su[2*BB*MM + b*MM + t]);
    float myinv = inv_from_nrm(g_nrm[b*HWN + n0 + t]);
    sinv[t] = myinv;
    __syncthreads();

    {
        int n = n0 + t;
        float scal = myinv * SCALE;
        float vals[MM];
        float s = 0.f;
        #pragma unroll
        for (int m = 0; m < MM; ++m) {
            vals[m] = expf(g_Z[(size_t)(b*MM + m)*HWN + n] * scal + us[m]);
            s += vals[m];
        }
        float is = 1.0f / s;
        #pragma unroll
        for (int m = 0; m < MM; ++m) sw[t*36 + m] = vals[m] * is;
    }
    __syncthreads();

    float acc[MM];
    #pragma unroll
    for (int m = 0; m < MM; ++m) acc[m] = 0.f;

    const int d  = dh*128 + (t & 127);
    const int nb = (t >> 7) * 128;
    for (int i = 0; i < 128; ++i) {
        int nn = nb + i;
        float xv = xp[(size_t)(b*HWN + n0 + nn)*DD + d] * sinv[nn];
        #pragma unroll
        for (int m4 = 0; m4 < 8; ++m4) {
            float4 w4 = *(float4*)(sw + nn*36 + m4*4);
            acc[m4*4+0] += xv * w4.x;
            acc[m4*4+1] += xv * w4.y;
            acc[m4*4+2] += xv * w4.z;
            acc[m4*4+3] += xv * w4.w;
        }
    }
    #pragma unroll
    for (int m = 0; m < MM; ++m)
        atomicAdd(&vt[(size_t)(b*MM + m)*DD + d], acc[m]);
}

// ------------------------------------------------------------------
extern "C" void kernel_launch(void* const* d_in, const int* in_sizes, int n_in,
                              void* d_out, int out_size) {
    (void)in_sizes; (void)n_in; (void)out_size;
    const float* x    = (const float*)d_in[0];   // [16,768,64,64]
    const float* W    = (const float*)d_in[1];   // [256,768]
    const float* bias = (const float*)d_in[2];   // [256]
    const float* v    = (const float*)d_in[3];   // [32,256]

    float* out = (float*)d_out;
    float* vt  = out;                 // v_tilde [16,32,256]
    float* xp  = out + VT_ELEMS;      // x_proj  [16,4096,256]

    cudaFuncSetAttribute(k1_mma, cudaFuncAttributeMaxDynamicSharedMemorySize, SMEM_SZ);

    k_pre1<<<608, 256>>>(v, W, vt);
    k_pre2<<<32, 256>>>(W, bias);
    k1_mma<<<dim3(32, 48), 256, SMEM_SZ>>>(x, bias, xp);
    kF<<<512, 128>>>(0, 0, 1);                 // S1 = sums for u1
    kF<<<512, 128>>>(0, BB*MM, 0);             // u1 -> v1 -> S2
    kF<<<512, 128>>>(BB*MM, 2*BB*MM, 0);       // u2 -> v2 -> S3
    k3<<<dim3(16, 32), 256>>>(xp, vt);         // u3 -> v3 + SIMT aggregation
}